// round 13
// baseline (speedup 1.0000x reference)
#include <cuda_runtime.h>
#include <cuda_fp16.h>
#include <cstdint>
#include <math.h>

#define B_SZ   2
#define S_LEN  2048
#define DM     2048
#define NH     32
#define NKV    8
#define DK     64
#define KVW    (NKV * DK)      // 512
#define MROWS  (B_SZ * S_LEN)  // 4096
#define NCAT   3072            // Q(2048) + K(512) + V(512)

// ---------------- scratch ----------------
__device__ __half g_xh[MROWS * DM];
__device__ __half g_Qh[MROWS * DM];
__device__ __half g_Kh[MROWS * KVW];
__device__ __half g_Vth[B_SZ * KVW * S_LEN];      // [b][dk][s]
__device__ __half g_Ch[MROWS * DM];
__device__ __half g_Wcat[NCAT * DM];              // [N][K] concat Q|K|V weights (hi)
__device__ __half g_Woh[DM * DM];
__device__ float  g_bcat[NCAT];

// ---------------- helpers ----------------
__device__ __forceinline__ void cp16(void* s, const void* g) {
    unsigned sa = (unsigned)__cvta_generic_to_shared(s);
    asm volatile("cp.async.cg.shared.global [%0], [%1], 16;\n" :: "r"(sa), "l"(g));
}
#define CP_COMMIT() asm volatile("cp.async.commit_group;\n")
#define CP_WAIT(n)  asm volatile("cp.async.wait_group %0;\n" :: "n"(n) : "memory")

__device__ __forceinline__ void mma16816(float* c, const unsigned* a, const unsigned* b) {
    asm volatile(
        "mma.sync.aligned.m16n8k16.row.col.f32.f16.f16.f32 "
        "{%0,%1,%2,%3}, {%4,%5,%6,%7}, {%8,%9}, {%0,%1,%2,%3};\n"
        : "+f"(c[0]), "+f"(c[1]), "+f"(c[2]), "+f"(c[3])
        : "r"(a[0]), "r"(a[1]), "r"(a[2]), "r"(a[3]), "r"(b[0]), "r"(b[1]));
}
__device__ __forceinline__ void ldsm_x4(unsigned* r, const void* p) {
    unsigned a = (unsigned)__cvta_generic_to_shared(p);
    asm volatile("ldmatrix.sync.aligned.m8n8.x4.shared.b16 {%0,%1,%2,%3}, [%4];\n"
                 : "=r"(r[0]), "=r"(r[1]), "=r"(r[2]), "=r"(r[3]) : "r"(a));
}
__device__ __forceinline__ unsigned pack2h(float v0, float v1) {
    __half2 h = __floats2half2_rn(v0, v1);
    return *(unsigned*)&h;
}

// ---------------------------------------------------------------------------
// fused prep: conv x -> fp16 | 4 weight transposes | bias concat. One launch.
// block dim (32, 8). block ranges:
//   [0, 8192)          conv x (8.4M elems, 1024 per block)
//   [8192, 12288)      Wq transpose  -> Wcat[0]
//   [12288, 13312)     Wk transpose  -> Wcat + 2048*DM
//   [13312, 14336)     Wv transpose  -> Wcat + 2560*DM
//   [14336, 18432)     Wo transpose  -> Woh
//   [18432, 18444)     bias concat
// ---------------------------------------------------------------------------
#define PREP_BLOCKS 18444

__global__ void prep_all(const float* __restrict__ x,
                         const float* __restrict__ Wq, const float* __restrict__ Wk,
                         const float* __restrict__ Wv, const float* __restrict__ Wo,
                         const float* __restrict__ bq, const float* __restrict__ bk,
                         const float* __restrict__ bv,
                         __half* __restrict__ xh, __half* __restrict__ Wcat,
                         __half* __restrict__ Woh, float* __restrict__ bcat)
{
    int bid = blockIdx.x;
    int tx = threadIdx.x, ty = threadIdx.y;
    int tid = ty * 32 + tx;

    if (bid < 8192) {                                    // conv x
        size_t i = ((size_t)bid * 256 + tid) * 4;
        float4 v = *(const float4*)(x + i);
        *(__half2*)(xh + i)     = __floats2half2_rn(v.x, v.y);
        *(__half2*)(xh + i + 2) = __floats2half2_rn(v.z, v.w);
        return;
    }
    bid -= 8192;
    if (bid >= 10240) {                                  // bias concat
        int i = (bid - 10240) * 256 + tid;
        float v = (i < 2048) ? bq[i] : (i < 2560 ? bk[i - 2048] : bv[i - 2560]);
        bcat[i] = v;
        return;
    }
    const float* W; __half* T; int N, tilesX;
    if (bid < 4096)      { W = Wq; T = Wcat;             N = DM;  tilesX = 64; }
    else if (bid < 5120) { bid -= 4096; W = Wk; T = Wcat + 2048 * DM; N = KVW; tilesX = 16; }
    else if (bid < 6144) { bid -= 5120; W = Wv; T = Wcat + 2560 * DM; N = KVW; tilesX = 16; }
    else                 { bid -= 6144; W = Wo; T = Woh;              N = DM;  tilesX = 64; }

    __shared__ float t[32][33];
    int bx = (bid % tilesX) * 32;   // n
    int by = (bid / tilesX) * 32;   // k
#pragma unroll
    for (int i = 0; i < 32; i += 8)
        t[ty + i][tx] = W[(size_t)(by + ty + i) * N + bx + tx];
    __syncthreads();
#pragma unroll
    for (int i = 0; i < 32; i += 8)
        T[(size_t)(bx + ty + i) * DM + by + tx] = __float2half_rn(t[tx][ty + i]);
}

// ---------------------------------------------------------------------------
// fp16 tensor-core GEMM: C = Ah[M,K] @ Bh^T[N,K] + bias
// 128x64 tiles (fine-grained to kill wave quantization), warp tile 32x32,
// persistent stride-grid, 2-stage cp.async, ldmatrix feed.
// mode 0: fp32 out (O projection). mode 1: fused QKV routing by column.
// smem/stage: A 128x40 + B 64x40 halves = 15360B; 2 stages = 30720B
// ---------------------------------------------------------------------------
#define GEMM_SMEM 30720
#define GEMM_GRID 296

__global__ __launch_bounds__(256, 2) void gemm_fp16(
    const __half* __restrict__ Ah, const __half* __restrict__ Bh,
    const float* __restrict__ bias, float* __restrict__ Cf,
    __half* __restrict__ Qh, __half* __restrict__ Kh, __half* __restrict__ Vth,
    int mode, int N, int K, int mTiles, int totTiles)
{
    extern __shared__ __half sm[];
    const int tid = threadIdx.x;
    const int T = K >> 5;
    const int w = tid >> 5, l = tid & 31;
    const int wm = (w & 3) * 32;          // 4 M-slices of 32
    const int wn = (w >> 2) * 32;         // 2 N-slices of 32
    const int qr = l >> 2, qc = (l & 3) * 2;
    const int arow = (l & 7) + ((l >> 3) & 1) * 8;
    const int acol = (l >> 4) * 8;
    const int brow = (l & 7) + ((l >> 4) & 1) * 8;
    const int bcol = ((l >> 3) & 1) * 8;

    for (int tIdx = blockIdx.x; tIdx < totTiles; tIdx += gridDim.x) {
        const int bm = (tIdx % mTiles) * 128;
        const int bn = (tIdx / mTiles) * 64;

        auto load_stage = [&](int s, int k0) {
            __half* base = sm + s * 7680;
#pragma unroll
            for (int t = 0; t < 3; t++) {
                int c = tid + t * 256;                 // 0..767
                if (c < 512) {                         // A: 128 rows x 32 halfs
                    int row = c >> 2, seg = (c & 3) << 3;
                    cp16(base + row * 40 + seg,
                         Ah + (size_t)(bm + row) * K + k0 + seg);
                } else {                               // B: 64 rows x 32 halfs
                    int j = c - 512;
                    int row = j >> 2, seg = (j & 3) << 3;
                    cp16(base + 5120 + row * 40 + seg,
                         Bh + (size_t)(bn + row) * K + k0 + seg);
                }
            }
        };

        float acc[2][4][4];
#pragma unroll
        for (int mi = 0; mi < 2; mi++)
#pragma unroll
            for (int ni = 0; ni < 4; ni++)
#pragma unroll
                for (int r = 0; r < 4; r++) acc[mi][ni][r] = 0.f;

        load_stage(0, 0);  CP_COMMIT();
        load_stage(1, 32); CP_COMMIT();

        for (int i = 0; i < T; i++) {
            if (i + 1 < T) CP_WAIT(1);
            else           CP_WAIT(0);
            __syncthreads();

            const __half* Ahs = sm + (i & 1) * 7680;
            const __half* Bhs = Ahs + 5120;

#pragma unroll
            for (int ks = 0; ks < 32; ks += 16) {
                unsigned ah[2][4];
#pragma unroll
                for (int mi = 0; mi < 2; mi++)
                    ldsm_x4(ah[mi], Ahs + (wm + mi * 16 + arow) * 40 + ks + acol);
#pragma unroll
                for (int p = 0; p < 2; p++) {
                    unsigned bh[4];
                    ldsm_x4(bh, Bhs + (wn + p * 16 + brow) * 40 + ks + bcol);
#pragma unroll
                    for (int mi = 0; mi < 2; mi++) {
                        mma16816(acc[mi][2 * p],     ah[mi], bh);
                        mma16816(acc[mi][2 * p + 1], ah[mi], bh + 2);
                    }
                }
            }
            __syncthreads();
            if (i + 2 < T) {
                load_stage(i & 1, (i + 2) * 32);
                CP_COMMIT();
            }
        }

#pragma unroll
        for (int mi = 0; mi < 2; mi++) {
#pragma unroll
            for (int ni = 0; ni < 4; ni++) {
                int r  = bm + wm + mi * 16 + qr;
                int cc = bn + wn + ni * 8 + qc;
                float b0 = bias[cc], b1 = bias[cc + 1];
                float v0 = acc[mi][ni][0] + b0, v1 = acc[mi][ni][1] + b1;
                float v2 = acc[mi][ni][2] + b0, v3 = acc[mi][ni][3] + b1;
                if (mode == 0) {
                    *(float2*)(Cf + (size_t)r * N + cc)       = make_float2(v0, v1);
                    *(float2*)(Cf + (size_t)(r + 8) * N + cc) = make_float2(v2, v3);
                } else if (cc < 2048) {             // Q
                    *(unsigned*)(Qh + (size_t)r * DM + cc)       = pack2h(v0, v1);
                    *(unsigned*)(Qh + (size_t)(r + 8) * DM + cc) = pack2h(v2, v3);
                } else if (cc < 2560) {             // K
                    int col = cc - 2048;
                    *(unsigned*)(Kh + (size_t)r * KVW + col)       = pack2h(v0, v1);
                    *(unsigned*)(Kh + (size_t)(r + 8) * KVW + col) = pack2h(v2, v3);
                } else {                            // V transposed [b][dk][s]
                    int col = cc - 2560;
                    int bb = r >> 11, sl = r & (S_LEN - 1);
                    size_t base = ((size_t)bb * KVW + col) * S_LEN;
                    Vth[base + sl]             = __float2half_rn(v0);
                    Vth[base + S_LEN + sl]     = __float2half_rn(v1);
                    Vth[base + sl + 8]         = __float2half_rn(v2);
                    Vth[base + S_LEN + sl + 8] = __float2half_rn(v3);
                }
            }
        }
    }
}

// ---------------------------------------------------------------------------
// fp16 flash attention (causal, GQA), hi-only, exp2-domain softmax.
// Largest mtile scheduled first. smem: Qh[128x72] | 2 stages {Kh,Vth}[64x72]
// ---------------------------------------------------------------------------
#define FL_SMEM ((9216 + 2 * 9216) * 2)   // 55296 bytes

__global__ __launch_bounds__(256) void gqa_flash_fp16(
    const __half* __restrict__ Qh_g, const __half* __restrict__ Kh_g,
    const __half* __restrict__ Vth_g, __half* __restrict__ Ch_g)
{
    extern __shared__ __half sb[];
    const int tid = threadIdx.x;
    const int w = tid >> 5, l = tid & 31;
    const int qr = l >> 2, qc = (l & 3) * 2;
    const int arow = (l & 7) + ((l >> 3) & 1) * 8;
    const int acol = (l >> 4) * 8;
    const int brow = (l & 7) + ((l >> 4) & 1) * 8;
    const int bcol = ((l >> 3) & 1) * 8;
    const int mtile = (gridDim.x - 1) - blockIdx.x;   // big blocks first
    const int h = blockIdx.y, b = blockIdx.z;
    const int kvh = h >> 2;
    const int m0 = mtile * 128;
    const int kvTiles = 2 * mtile + 2;
    const int lastTile = 2 * mtile + (w >> 2);

    const __half* Qph = Qh_g + ((size_t)(b * S_LEN + m0)) * DM + h * 64;
#pragma unroll
    for (int t = 0; t < 4; t++) {
        int idx = tid + t * 256;
        int row = idx >> 3, seg = (idx & 7) * 8;
        cp16(sb + row * 72 + seg, Qph + (size_t)row * DM + seg);
    }

    auto load_kv = [&](int sidx, int jt) {
        __half* st = sb + 9216 + sidx * 9216;
        const int k0 = jt * 64;
        const __half* Kg = Kh_g + ((size_t)(b * S_LEN + k0)) * KVW + kvh * 64;
        const __half* Vg = Vth_g + ((size_t)b * KVW + kvh * 64) * S_LEN + k0;
#pragma unroll
        for (int t = 0; t < 2; t++) {
            int idx = tid + t * 256;
            int row = idx >> 3, seg = (idx & 7) * 8;
            cp16(st + row * 72 + seg,        Kg + (size_t)row * KVW + seg);
            cp16(st + 4608 + row * 72 + seg, Vg + (size_t)row * S_LEN + seg);
        }
    };

    load_kv(0, 0); CP_COMMIT();
    load_kv(1, 1); CP_COMMIT();
    CP_WAIT(1);
    __syncthreads();

    unsigned aqh[4][4];
#pragma unroll
    for (int j = 0; j < 4; j++)
        ldsm_x4(aqh[j], sb + (w * 16 + arow) * 72 + j * 16 + acol);

    float o[8][4];
#pragma unroll
    for (int n = 0; n < 8; n++)
#pragma unroll
        for (int r = 0; r < 4; r++) o[n][r] = 0.f;
    float mrow0 = -INFINITY, mrow1 = -INFINITY, lrow0 = 0.f, lrow1 = 0.f;

    const int r0 = m0 + w * 16 + qr;
    const int r1 = r0 + 8;

    for (int jt = 0; jt < kvTiles; jt++) {
        if (jt > 0) {
            if (jt + 1 < kvTiles) CP_WAIT(1); else CP_WAIT(0);
            __syncthreads();
        }
        const __half* st = sb + 9216 + (jt & 1) * 9216;

        if (jt <= lastTile) {
            const int k0 = jt * 64;
            float s[8][4];
#pragma unroll
            for (int n = 0; n < 8; n++)
#pragma unroll
                for (int r = 0; r < 4; r++) s[n][r] = 0.f;

            // S = Qh Kh^T
#pragma unroll
            for (int j = 0; j < 4; j++) {
#pragma unroll
                for (int p = 0; p < 4; p++) {
                    unsigned bh[4];
                    ldsm_x4(bh, st + (p * 16 + brow) * 72 + j * 16 + bcol);
                    mma16816(s[2 * p],     aqh[j], bh);
                    mma16816(s[2 * p + 1], aqh[j], bh + 2);
                }
            }

            // scale into exp2 domain: rs = log2(e)/8
            const float rs = 0.18033688f;
            if (k0 + 63 > m0 + w * 16) {
#pragma unroll
                for (int n = 0; n < 8; n++) {
                    int c0 = k0 + n * 8 + qc;
                    s[n][0] = (c0     > r0) ? -1e30f : s[n][0] * rs;
                    s[n][1] = (c0 + 1 > r0) ? -1e30f : s[n][1] * rs;
                    s[n][2] = (c0     > r1) ? -1e30f : s[n][2] * rs;
                    s[n][3] = (c0 + 1 > r1) ? -1e30f : s[n][3] * rs;
                }
            } else {
#pragma unroll
                for (int n = 0; n < 8; n++)
#pragma unroll
                    for (int r = 0; r < 4; r++) s[n][r] *= rs;
            }

            float mx0 = -1e30f, mx1 = -1e30f;
#pragma unroll
            for (int n = 0; n < 8; n++) {
                mx0 = fmaxf(mx0, fmaxf(s[n][0], s[n][1]));
                mx1 = fmaxf(mx1, fmaxf(s[n][2], s[n][3]));
            }
            mx0 = fmaxf(mx0, __shfl_xor_sync(0xffffffffu, mx0, 1));
            mx0 = fmaxf(mx0, __shfl_xor_sync(0xffffffffu, mx0, 2));
            mx1 = fmaxf(mx1, __shfl_xor_sync(0xffffffffu, mx1, 1));
            mx1 = fmaxf(mx1, __shfl_xor_sync(0xffffffffu, mx1, 2));
            float mn0 = fmaxf(mrow0, mx0), mn1 = fmaxf(mrow1, mx1);
            float cr0 = exp2f(mrow0 - mn0), cr1 = exp2f(mrow1 - mn1);
            float sum0 = 0.f, sum1 = 0.f;
#pragma unroll
            for (int n = 0; n < 8; n++) {
                s[n][0] = exp2f(s[n][0] - mn0);
                s[n][1] = exp2f(s[n][1] - mn0);
                s[n][2] = exp2f(s[n][2] - mn1);
                s[n][3] = exp2f(s[n][3] - mn1);
                sum0 += s[n][0] + s[n][1];
                sum1 += s[n][2] + s[n][3];
            }
            sum0 += __shfl_xor_sync(0xffffffffu, sum0, 1);
            sum0 += __shfl_xor_sync(0xffffffffu, sum0, 2);
            sum1 += __shfl_xor_sync(0xffffffffu, sum1, 1);
            sum1 += __shfl_xor_sync(0xffffffffu, sum1, 2);
            lrow0 = lrow0 * cr0 + sum0;
            lrow1 = lrow1 * cr1 + sum1;
            mrow0 = mn0; mrow1 = mn1;
#pragma unroll
            for (int n = 0; n < 8; n++) {
                o[n][0] *= cr0; o[n][1] *= cr0;
                o[n][2] *= cr1; o[n][3] *= cr1;
            }

            unsigned pah[4][4];
#pragma unroll
            for (int j = 0; j < 4; j++) {
                pah[j][0] = pack2h(s[2 * j][0],     s[2 * j][1]);
                pah[j][1] = pack2h(s[2 * j][2],     s[2 * j][3]);
                pah[j][2] = pack2h(s[2 * j + 1][0], s[2 * j + 1][1]);
                pah[j][3] = pack2h(s[2 * j + 1][2], s[2 * j + 1][3]);
            }

            // O += Ph Vh
#pragma unroll
            for (int j = 0; j < 4; j++) {
#pragma unroll
                for (int p = 0; p < 4; p++) {
                    unsigned bh[4];
                    ldsm_x4(bh, st + 4608 + (p * 16 + brow) * 72 + j * 16 + bcol);
                    mma16816(o[2 * p],     pah[j], bh);
                    mma16816(o[2 * p + 1], pah[j], bh + 2);
                }
            }
        }

        __syncthreads();
        if (jt + 2 < kvTiles) {
            load_kv(jt & 1, jt + 2);
            CP_COMMIT();
        }
    }

    float inv0 = 1.f / lrow0, inv1 = 1.f / lrow1;
    size_t base0 = ((size_t)(b * S_LEN) + r0) * DM + h * 64;
    size_t base1 = ((size_t)(b * S_LEN) + r1) * DM + h * 64;
#pragma unroll
    for (int n = 0; n < 8; n++) {
        *(__half2*)(Ch_g + base0 + n * 8 + qc) = __floats2half2_rn(o[n][0] * inv0, o[n][1] * inv0);
        *(__half2*)(Ch_g + base1 + n * 8 + qc) = __floats2half2_rn(o[n][2] * inv1, o[n][3] * inv1);
    }
}

// ---------------------------------------------------------------------------
extern "C" void kernel_launch(void* const* d_in, const int* in_sizes, int n_in,
                              void* d_out, int out_size)
{
    (void)in_sizes; (void)n_in; (void)out_size;
    const float* x  = (const float*)d_in[0];
    const float* Wq = (const float*)d_in[2];
    const float* bq = (const float*)d_in[3];
    const float* Wk = (const float*)d_in[4];
    const float* bk = (const float*)d_in[5];
    const float* Wv = (const float*)d_in[6];
    const float* bv = (const float*)d_in[7];
    const float* Wo = (const float*)d_in[8];
    const float* bo = (const float*)d_in[9];
    float* out = (float*)d_out;

    __half *xh, *Qh, *Kh, *Vth, *Ch, *Wcat, *Woh;
    float* bcat;
    cudaGetSymbolAddress((void**)&xh, g_xh);
    cudaGetSymbolAddress((void**)&Qh, g_Qh);
    cudaGetSymbolAddress((void**)&Kh, g_Kh);
    cudaGetSymbolAddress((void**)&Vth, g_Vth);
    cudaGetSymbolAddress((void**)&Ch, g_Ch);
    cudaGetSymbolAddress((void**)&Wcat, g_Wcat);
    cudaGetSymbolAddress((void**)&Woh, g_Woh);
    cudaGetSymbolAddress((void**)&bcat, g_bcat);

    cudaFuncSetAttribute(gemm_fp16,
                         cudaFuncAttributeMaxDynamicSharedMemorySize, GEMM_SMEM);
    cudaFuncSetAttribute(gqa_flash_fp16,
                         cudaFuncAttributeMaxDynamicSharedMemorySize, FL_SMEM);

    // fused prep (one launch)
    prep_all<<<PREP_BLOCKS, dim3(32, 8)>>>(x, Wq, Wk, Wv, Wo, bq, bk, bv,
                                           xh, Wcat, Woh, bcat);

    // fused QKV projection: M=4096, N=3072, tiles 128x64 -> 32 x 48 = 1536
    gemm_fp16<<<GEMM_GRID, 256, GEMM_SMEM>>>(
        xh, Wcat, bcat, nullptr, Qh, Kh, Vth, 1, NCAT, DM, 32, 1536);

    // attention
    gqa_flash_fp16<<<dim3(S_LEN / 128, NH, B_SZ), 256, FL_SMEM>>>(
        Qh, Kh, Vth, Ch);

    // output projection: M=4096, N=2048, tiles 128x64 -> 32 x 32 = 1024
    gemm_fp16<<<GEMM_GRID, 256, GEMM_SMEM>>>(
        Ch, Woh, bo, out, nullptr, nullptr, nullptr, 0, DM, DM, 32, 1024);
}

// round 14
// speedup vs baseline: 1.0505x; 1.0505x over previous
#include <cuda_runtime.h>
#include <cuda_fp16.h>
#include <cstdint>
#include <math.h>

#define B_SZ   2
#define S_LEN  2048
#define DM     2048
#define NH     32
#define NKV    8
#define DK     64
#define KVW    (NKV * DK)      // 512
#define MROWS  (B_SZ * S_LEN)  // 4096
#define NCAT   3072            // Q(2048) + K(512) + V(512)

// ---------------- scratch ----------------
__device__ __half g_xh[MROWS * DM];
__device__ __half g_Qh[MROWS * DM];
__device__ __half g_Kh[MROWS * KVW];
__device__ __half g_Vth[B_SZ * KVW * S_LEN];      // [b][dk][s]
__device__ __half g_Ch[MROWS * DM];
__device__ __half g_Wcat[NCAT * DM];              // [N][K] concat Q|K|V weights (hi)
__device__ __half g_Woh[DM * DM];
__device__ float  g_bcat[NCAT];

// ---------------- helpers ----------------
__device__ __forceinline__ void cp16(void* s, const void* g) {
    unsigned sa = (unsigned)__cvta_generic_to_shared(s);
    asm volatile("cp.async.cg.shared.global [%0], [%1], 16;\n" :: "r"(sa), "l"(g));
}
#define CP_COMMIT() asm volatile("cp.async.commit_group;\n")
#define CP_WAIT(n)  asm volatile("cp.async.wait_group %0;\n" :: "n"(n) : "memory")

__device__ __forceinline__ void mma16816(float* c, const unsigned* a, const unsigned* b) {
    asm volatile(
        "mma.sync.aligned.m16n8k16.row.col.f32.f16.f16.f32 "
        "{%0,%1,%2,%3}, {%4,%5,%6,%7}, {%8,%9}, {%0,%1,%2,%3};\n"
        : "+f"(c[0]), "+f"(c[1]), "+f"(c[2]), "+f"(c[3])
        : "r"(a[0]), "r"(a[1]), "r"(a[2]), "r"(a[3]), "r"(b[0]), "r"(b[1]));
}
__device__ __forceinline__ void ldsm_x4(unsigned* r, const void* p) {
    unsigned a = (unsigned)__cvta_generic_to_shared(p);
    asm volatile("ldmatrix.sync.aligned.m8n8.x4.shared.b16 {%0,%1,%2,%3}, [%4];\n"
                 : "=r"(r[0]), "=r"(r[1]), "=r"(r[2]), "=r"(r[3]) : "r"(a));
}
__device__ __forceinline__ unsigned pack2h(float v0, float v1) {
    __half2 h = __floats2half2_rn(v0, v1);
    return *(unsigned*)&h;
}

// ---------------------------------------------------------------------------
// fused prep (one launch) — unchanged from R13
// ---------------------------------------------------------------------------
#define PREP_BLOCKS 18444

__global__ void prep_all(const float* __restrict__ x,
                         const float* __restrict__ Wq, const float* __restrict__ Wk,
                         const float* __restrict__ Wv, const float* __restrict__ Wo,
                         const float* __restrict__ bq, const float* __restrict__ bk,
                         const float* __restrict__ bv,
                         __half* __restrict__ xh, __half* __restrict__ Wcat,
                         __half* __restrict__ Woh, float* __restrict__ bcat)
{
    int bid = blockIdx.x;
    int tx = threadIdx.x, ty = threadIdx.y;
    int tid = ty * 32 + tx;

    if (bid < 8192) {                                    // conv x
        size_t i = ((size_t)bid * 256 + tid) * 4;
        float4 v = *(const float4*)(x + i);
        *(__half2*)(xh + i)     = __floats2half2_rn(v.x, v.y);
        *(__half2*)(xh + i + 2) = __floats2half2_rn(v.z, v.w);
        return;
    }
    bid -= 8192;
    if (bid >= 10240) {                                  // bias concat
        int i = (bid - 10240) * 256 + tid;
        float v = (i < 2048) ? bq[i] : (i < 2560 ? bk[i - 2048] : bv[i - 2560]);
        bcat[i] = v;
        return;
    }
    const float* W; __half* T; int N, tilesX;
    if (bid < 4096)      { W = Wq; T = Wcat;             N = DM;  tilesX = 64; }
    else if (bid < 5120) { bid -= 4096; W = Wk; T = Wcat + 2048 * DM; N = KVW; tilesX = 16; }
    else if (bid < 6144) { bid -= 5120; W = Wv; T = Wcat + 2560 * DM; N = KVW; tilesX = 16; }
    else                 { bid -= 6144; W = Wo; T = Woh;              N = DM;  tilesX = 64; }

    __shared__ float t[32][33];
    int bx = (bid % tilesX) * 32;
    int by = (bid / tilesX) * 32;
#pragma unroll
    for (int i = 0; i < 32; i += 8)
        t[ty + i][tx] = W[(size_t)(by + ty + i) * N + bx + tx];
    __syncthreads();
#pragma unroll
    for (int i = 0; i < 32; i += 8)
        T[(size_t)(bx + ty + i) * DM + by + tx] = __float2half_rn(t[tx][ty + i]);
}

// ---------------------------------------------------------------------------
// fp16 GEMM: 128x64 tiles, persistent grid, 3-stage ring, ONE sync per chunk.
// smem/stage: A 128x40 + B 64x40 halves = 15360B; 3 stages = 46080B
// ---------------------------------------------------------------------------
#define GEMM_SMEM 46080
#define GEMM_GRID 296

__global__ __launch_bounds__(256, 2) void gemm_fp16(
    const __half* __restrict__ Ah, const __half* __restrict__ Bh,
    const float* __restrict__ bias, float* __restrict__ Cf,
    __half* __restrict__ Qh, __half* __restrict__ Kh, __half* __restrict__ Vth,
    int mode, int N, int K, int mTiles, int totTiles)
{
    extern __shared__ __half sm[];
    const int tid = threadIdx.x;
    const int T = K >> 5;
    const int w = tid >> 5, l = tid & 31;
    const int wm = (w & 3) * 32;
    const int wn = (w >> 2) * 32;
    const int qr = l >> 2, qc = (l & 3) * 2;
    const int arow = (l & 7) + ((l >> 3) & 1) * 8;
    const int acol = (l >> 4) * 8;
    const int brow = (l & 7) + ((l >> 4) & 1) * 8;
    const int bcol = ((l >> 3) & 1) * 8;

    for (int tIdx = blockIdx.x; tIdx < totTiles; tIdx += gridDim.x) {
        const int bm = (tIdx % mTiles) * 128;
        const int bn = (tIdx / mTiles) * 64;

        auto load_stage = [&](int s, int k0) {
            __half* base = sm + s * 7680;
#pragma unroll
            for (int t = 0; t < 3; t++) {
                int c = tid + t * 256;
                if (c < 512) {
                    int row = c >> 2, seg = (c & 3) << 3;
                    cp16(base + row * 40 + seg,
                         Ah + (size_t)(bm + row) * K + k0 + seg);
                } else {
                    int j = c - 512;
                    int row = j >> 2, seg = (j & 3) << 3;
                    cp16(base + 5120 + row * 40 + seg,
                         Bh + (size_t)(bn + row) * K + k0 + seg);
                }
            }
        };

        float acc[2][4][4];
#pragma unroll
        for (int mi = 0; mi < 2; mi++)
#pragma unroll
            for (int ni = 0; ni < 4; ni++)
#pragma unroll
                for (int r = 0; r < 4; r++) acc[mi][ni][r] = 0.f;

        load_stage(0, 0);  CP_COMMIT();
        load_stage(1, 32); CP_COMMIT();

        int sIdx = 0;   // i % 3
        for (int i = 0; i < T; i++) {
            if (i < T - 1) CP_WAIT(1);
            else           CP_WAIT(0);
            __syncthreads();
            if (i + 2 < T) {   // load stage (i+2)%3 == (i-1)%3 (readers done at sync)
                int ls = sIdx + 2; if (ls >= 3) ls -= 3;
                load_stage(ls, (i + 2) * 32);
                CP_COMMIT();
            }

            const __half* Ahs = sm + sIdx * 7680;
            const __half* Bhs = Ahs + 5120;

#pragma unroll
            for (int ks = 0; ks < 32; ks += 16) {
                unsigned ah[2][4];
#pragma unroll
                for (int mi = 0; mi < 2; mi++)
                    ldsm_x4(ah[mi], Ahs + (wm + mi * 16 + arow) * 40 + ks + acol);
#pragma unroll
                for (int p = 0; p < 2; p++) {
                    unsigned bh[4];
                    ldsm_x4(bh, Bhs + (wn + p * 16 + brow) * 40 + ks + bcol);
#pragma unroll
                    for (int mi = 0; mi < 2; mi++) {
                        mma16816(acc[mi][2 * p],     ah[mi], bh);
                        mma16816(acc[mi][2 * p + 1], ah[mi], bh + 2);
                    }
                }
            }
            if (++sIdx == 3) sIdx = 0;
        }

#pragma unroll
        for (int mi = 0; mi < 2; mi++) {
#pragma unroll
            for (int ni = 0; ni < 4; ni++) {
                int r  = bm + wm + mi * 16 + qr;
                int cc = bn + wn + ni * 8 + qc;
                float b0 = bias[cc], b1 = bias[cc + 1];
                float v0 = acc[mi][ni][0] + b0, v1 = acc[mi][ni][1] + b1;
                float v2 = acc[mi][ni][2] + b0, v3 = acc[mi][ni][3] + b1;
                if (mode == 0) {
                    *(float2*)(Cf + (size_t)r * N + cc)       = make_float2(v0, v1);
                    *(float2*)(Cf + (size_t)(r + 8) * N + cc) = make_float2(v2, v3);
                } else if (cc < 2048) {             // Q
                    *(unsigned*)(Qh + (size_t)r * DM + cc)       = pack2h(v0, v1);
                    *(unsigned*)(Qh + (size_t)(r + 8) * DM + cc) = pack2h(v2, v3);
                } else if (cc < 2560) {             // K
                    int col = cc - 2048;
                    *(unsigned*)(Kh + (size_t)r * KVW + col)       = pack2h(v0, v1);
                    *(unsigned*)(Kh + (size_t)(r + 8) * KVW + col) = pack2h(v2, v3);
                } else {                            // V transposed [b][dk][s]
                    int col = cc - 2560;
                    int bb = r >> 11, sl = r & (S_LEN - 1);
                    size_t base = ((size_t)bb * KVW + col) * S_LEN;
                    Vth[base + sl]             = __float2half_rn(v0);
                    Vth[base + S_LEN + sl]     = __float2half_rn(v1);
                    Vth[base + sl + 8]         = __float2half_rn(v2);
                    Vth[base + S_LEN + sl + 8] = __float2half_rn(v3);
                }
            }
        }
        __syncthreads();   // protect stage buffers before next tile's prologue
    }
}

// ---------------------------------------------------------------------------
// fp16 flash attention (causal, GQA), hi-only, exp2 softmax.
// 3-stage K/V ring, ONE sync per kv tile.
// smem: Qh[128x72] @0 | stages {Kh,Vth}[64x72] @9216 + s*9216 (halves)
// ---------------------------------------------------------------------------
#define FL_SMEM ((9216 + 3 * 9216) * 2)   // 73728 bytes

__global__ __launch_bounds__(256) void gqa_flash_fp16(
    const __half* __restrict__ Qh_g, const __half* __restrict__ Kh_g,
    const __half* __restrict__ Vth_g, __half* __restrict__ Ch_g)
{
    extern __shared__ __half sb[];
    const int tid = threadIdx.x;
    const int w = tid >> 5, l = tid & 31;
    const int qr = l >> 2, qc = (l & 3) * 2;
    const int arow = (l & 7) + ((l >> 3) & 1) * 8;
    const int acol = (l >> 4) * 8;
    const int brow = (l & 7) + ((l >> 4) & 1) * 8;
    const int bcol = ((l >> 3) & 1) * 8;
    const int mtile = (gridDim.x - 1) - blockIdx.x;   // big blocks first
    const int h = blockIdx.y, b = blockIdx.z;
    const int kvh = h >> 2;
    const int m0 = mtile * 128;
    const int kvTiles = 2 * mtile + 2;
    const int lastTile = 2 * mtile + (w >> 2);

    const __half* Qph = Qh_g + ((size_t)(b * S_LEN + m0)) * DM + h * 64;
#pragma unroll
    for (int t = 0; t < 4; t++) {
        int idx = tid + t * 256;
        int row = idx >> 3, seg = (idx & 7) * 8;
        cp16(sb + row * 72 + seg, Qph + (size_t)row * DM + seg);
    }

    auto load_kv = [&](int sidx, int jt) {
        __half* st = sb + 9216 + sidx * 9216;
        const int k0 = jt * 64;
        const __half* Kg = Kh_g + ((size_t)(b * S_LEN + k0)) * KVW + kvh * 64;
        const __half* Vg = Vth_g + ((size_t)b * KVW + kvh * 64) * S_LEN + k0;
#pragma unroll
        for (int t = 0; t < 2; t++) {
            int idx = tid + t * 256;
            int row = idx >> 3, seg = (idx & 7) * 8;
            cp16(st + row * 72 + seg,        Kg + (size_t)row * KVW + seg);
            cp16(st + 4608 + row * 72 + seg, Vg + (size_t)row * S_LEN + seg);
        }
    };

    load_kv(0, 0); CP_COMMIT();
    load_kv(1, 1); CP_COMMIT();

    unsigned aqh[4][4];
    float o[8][4];
#pragma unroll
    for (int n = 0; n < 8; n++)
#pragma unroll
        for (int r = 0; r < 4; r++) o[n][r] = 0.f;
    float mrow0 = -INFINITY, mrow1 = -INFINITY, lrow0 = 0.f, lrow1 = 0.f;

    const int r0 = m0 + w * 16 + qr;
    const int r1 = r0 + 8;

    int sIdx = 0;
    for (int jt = 0; jt < kvTiles; jt++) {
        if (jt < kvTiles - 1) CP_WAIT(1);
        else                  CP_WAIT(0);
        __syncthreads();
        if (jt + 2 < kvTiles) {   // fill stage (jt+2)%3 == (jt-1)%3
            int ls = sIdx + 2; if (ls >= 3) ls -= 3;
            load_kv(ls, jt + 2);
            CP_COMMIT();
        }
        if (jt == 0) {            // Q arrived with stage-0 group
#pragma unroll
            for (int j = 0; j < 4; j++)
                ldsm_x4(aqh[j], sb + (w * 16 + arow) * 72 + j * 16 + acol);
        }
        const __half* st = sb + 9216 + sIdx * 9216;

        if (jt <= lastTile) {
            const int k0 = jt * 64;
            float s[8][4];
#pragma unroll
            for (int n = 0; n < 8; n++)
#pragma unroll
                for (int r = 0; r < 4; r++) s[n][r] = 0.f;

            // S = Qh Kh^T
#pragma unroll
            for (int j = 0; j < 4; j++) {
#pragma unroll
                for (int p = 0; p < 4; p++) {
                    unsigned bh[4];
                    ldsm_x4(bh, st + (p * 16 + brow) * 72 + j * 16 + bcol);
                    mma16816(s[2 * p],     aqh[j], bh);
                    mma16816(s[2 * p + 1], aqh[j], bh + 2);
                }
            }

            // scale into exp2 domain: rs = log2(e)/8
            const float rs = 0.18033688f;
            if (k0 + 63 > m0 + w * 16) {
#pragma unroll
                for (int n = 0; n < 8; n++) {
                    int c0 = k0 + n * 8 + qc;
                    s[n][0] = (c0     > r0) ? -1e30f : s[n][0] * rs;
                    s[n][1] = (c0 + 1 > r0) ? -1e30f : s[n][1] * rs;
                    s[n][2] = (c0     > r1) ? -1e30f : s[n][2] * rs;
                    s[n][3] = (c0 + 1 > r1) ? -1e30f : s[n][3] * rs;
                }
            } else {
#pragma unroll
                for (int n = 0; n < 8; n++)
#pragma unroll
                    for (int r = 0; r < 4; r++) s[n][r] *= rs;
            }

            float mx0 = -1e30f, mx1 = -1e30f;
#pragma unroll
            for (int n = 0; n < 8; n++) {
                mx0 = fmaxf(mx0, fmaxf(s[n][0], s[n][1]));
                mx1 = fmaxf(mx1, fmaxf(s[n][2], s[n][3]));
            }
            mx0 = fmaxf(mx0, __shfl_xor_sync(0xffffffffu, mx0, 1));
            mx0 = fmaxf(mx0, __shfl_xor_sync(0xffffffffu, mx0, 2));
            mx1 = fmaxf(mx1, __shfl_xor_sync(0xffffffffu, mx1, 1));
            mx1 = fmaxf(mx1, __shfl_xor_sync(0xffffffffu, mx1, 2));
            float mn0 = fmaxf(mrow0, mx0), mn1 = fmaxf(mrow1, mx1);
            float cr0 = exp2f(mrow0 - mn0), cr1 = exp2f(mrow1 - mn1);
            float sum0 = 0.f, sum1 = 0.f;
#pragma unroll
            for (int n = 0; n < 8; n++) {
                s[n][0] = exp2f(s[n][0] - mn0);
                s[n][1] = exp2f(s[n][1] - mn0);
                s[n][2] = exp2f(s[n][2] - mn1);
                s[n][3] = exp2f(s[n][3] - mn1);
                sum0 += s[n][0] + s[n][1];
                sum1 += s[n][2] + s[n][3];
            }
            sum0 += __shfl_xor_sync(0xffffffffu, sum0, 1);
            sum0 += __shfl_xor_sync(0xffffffffu, sum0, 2);
            sum1 += __shfl_xor_sync(0xffffffffu, sum1, 1);
            sum1 += __shfl_xor_sync(0xffffffffu, sum1, 2);
            lrow0 = lrow0 * cr0 + sum0;
            lrow1 = lrow1 * cr1 + sum1;
            mrow0 = mn0; mrow1 = mn1;
#pragma unroll
            for (int n = 0; n < 8; n++) {
                o[n][0] *= cr0; o[n][1] *= cr0;
                o[n][2] *= cr1; o[n][3] *= cr1;
            }

            unsigned pah[4][4];
#pragma unroll
            for (int j = 0; j < 4; j++) {
                pah[j][0] = pack2h(s[2 * j][0],     s[2 * j][1]);
                pah[j][1] = pack2h(s[2 * j][2],     s[2 * j][3]);
                pah[j][2] = pack2h(s[2 * j + 1][0], s[2 * j + 1][1]);
                pah[j][3] = pack2h(s[2 * j + 1][2], s[2 * j + 1][3]);
            }

            // O += Ph Vh
#pragma unroll
            for (int j = 0; j < 4; j++) {
#pragma unroll
                for (int p = 0; p < 4; p++) {
                    unsigned bh[4];
                    ldsm_x4(bh, st + 4608 + (p * 16 + brow) * 72 + j * 16 + bcol);
                    mma16816(o[2 * p],     pah[j], bh);
                    mma16816(o[2 * p + 1], pah[j], bh + 2);
                }
            }
        }
        if (++sIdx == 3) sIdx = 0;
    }

    float inv0 = 1.f / lrow0, inv1 = 1.f / lrow1;
    size_t base0 = ((size_t)(b * S_LEN) + r0) * DM + h * 64;
    size_t base1 = ((size_t)(b * S_LEN) + r1) * DM + h * 64;
#pragma unroll
    for (int n = 0; n < 8; n++) {
        *(__half2*)(Ch_g + base0 + n * 8 + qc) = __floats2half2_rn(o[n][0] * inv0, o[n][1] * inv0);
        *(__half2*)(Ch_g + base1 + n * 8 + qc) = __floats2half2_rn(o[n][2] * inv1, o[n][3] * inv1);
    }
}

// ---------------------------------------------------------------------------
extern "C" void kernel_launch(void* const* d_in, const int* in_sizes, int n_in,
                              void* d_out, int out_size)
{
    (void)in_sizes; (void)n_in; (void)out_size;
    const float* x  = (const float*)d_in[0];
    const float* Wq = (const float*)d_in[2];
    const float* bq = (const float*)d_in[3];
    const float* Wk = (const float*)d_in[4];
    const float* bk = (const float*)d_in[5];
    const float* Wv = (const float*)d_in[6];
    const float* bv = (const float*)d_in[7];
    const float* Wo = (const float*)d_in[8];
    const float* bo = (const float*)d_in[9];
    float* out = (float*)d_out;

    __half *xh, *Qh, *Kh, *Vth, *Ch, *Wcat, *Woh;
    float* bcat;
    cudaGetSymbolAddress((void**)&xh, g_xh);
    cudaGetSymbolAddress((void**)&Qh, g_Qh);
    cudaGetSymbolAddress((void**)&Kh, g_Kh);
    cudaGetSymbolAddress((void**)&Vth, g_Vth);
    cudaGetSymbolAddress((void**)&Ch, g_Ch);
    cudaGetSymbolAddress((void**)&Wcat, g_Wcat);
    cudaGetSymbolAddress((void**)&Woh, g_Woh);
    cudaGetSymbolAddress((void**)&bcat, g_bcat);

    cudaFuncSetAttribute(gemm_fp16,
                         cudaFuncAttributeMaxDynamicSharedMemorySize, GEMM_SMEM);
    cudaFuncSetAttribute(gqa_flash_fp16,
                         cudaFuncAttributeMaxDynamicSharedMemorySize, FL_SMEM);

    // fused prep
    prep_all<<<PREP_BLOCKS, dim3(32, 8)>>>(x, Wq, Wk, Wv, Wo, bq, bk, bv,
                                           xh, Wcat, Woh, bcat);

    // fused QKV projection: tiles 128x64 -> 32 x 48 = 1536
    gemm_fp16<<<GEMM_GRID, 256, GEMM_SMEM>>>(
        xh, Wcat, bcat, nullptr, Qh, Kh, Vth, 1, NCAT, DM, 32, 1536);

    // attention
    gqa_flash_fp16<<<dim3(S_LEN / 128, NH, B_SZ), 256, FL_SMEM>>>(
        Qh, Kh, Vth, Ch);

    // output projection: tiles 128x64 -> 32 x 32 = 1024
    gemm_fp16<<<GEMM_GRID, 256, GEMM_SMEM>>>(
        Ch, Woh, bo, out, nullptr, nullptr, nullptr, 0, DM, DM, 32, 1024);
}

// round 15
// speedup vs baseline: 1.1381x; 1.0834x over previous
#include <cuda_runtime.h>
#include <cuda_fp16.h>
#include <cstdint>
#include <math.h>

#define B_SZ   2
#define S_LEN  2048
#define DM     2048
#define NH     32
#define NKV    8
#define DK     64
#define KVW    (NKV * DK)      // 512
#define MROWS  (B_SZ * S_LEN)  // 4096
#define NCAT   3072            // Q(2048) + K(512) + V(512)

// ---------------- scratch ----------------
__device__ __half g_xh[MROWS * DM];
__device__ __half g_Qh[MROWS * DM];
__device__ __half g_Kh[MROWS * KVW];
__device__ __half g_Vth[B_SZ * KVW * S_LEN];      // [b][dk][s]
__device__ __half g_Ch[MROWS * DM];
__device__ __half g_Wcat[NCAT * DM];              // [N][K] concat Q|K|V weights (hi)
__device__ __half g_Woh[DM * DM];
__device__ float  g_bcat[NCAT];

// ---------------- helpers ----------------
__device__ __forceinline__ void cp16(void* s, const void* g) {
    unsigned sa = (unsigned)__cvta_generic_to_shared(s);
    asm volatile("cp.async.cg.shared.global [%0], [%1], 16;\n" :: "r"(sa), "l"(g));
}
#define CP_COMMIT() asm volatile("cp.async.commit_group;\n")
#define CP_WAIT(n)  asm volatile("cp.async.wait_group %0;\n" :: "n"(n) : "memory")

__device__ __forceinline__ void mma16816(float* c, const unsigned* a, const unsigned* b) {
    asm volatile(
        "mma.sync.aligned.m16n8k16.row.col.f32.f16.f16.f32 "
        "{%0,%1,%2,%3}, {%4,%5,%6,%7}, {%8,%9}, {%0,%1,%2,%3};\n"
        : "+f"(c[0]), "+f"(c[1]), "+f"(c[2]), "+f"(c[3])
        : "r"(a[0]), "r"(a[1]), "r"(a[2]), "r"(a[3]), "r"(b[0]), "r"(b[1]));
}
__device__ __forceinline__ void ldsm_x4(unsigned* r, const void* p) {
    unsigned a = (unsigned)__cvta_generic_to_shared(p);
    asm volatile("ldmatrix.sync.aligned.m8n8.x4.shared.b16 {%0,%1,%2,%3}, [%4];\n"
                 : "=r"(r[0]), "=r"(r[1]), "=r"(r[2]), "=r"(r[3]) : "r"(a));
}
__device__ __forceinline__ unsigned pack2h(float v0, float v1) {
    __half2 h = __floats2half2_rn(v0, v1);
    return *(unsigned*)&h;
}

// ---------------------------------------------------------------------------
// fused prep (one launch)
// ---------------------------------------------------------------------------
#define PREP_BLOCKS 18444

__global__ void prep_all(const float* __restrict__ x,
                         const float* __restrict__ Wq, const float* __restrict__ Wk,
                         const float* __restrict__ Wv, const float* __restrict__ Wo,
                         const float* __restrict__ bq, const float* __restrict__ bk,
                         const float* __restrict__ bv,
                         __half* __restrict__ xh, __half* __restrict__ Wcat,
                         __half* __restrict__ Woh, float* __restrict__ bcat)
{
    int bid = blockIdx.x;
    int tx = threadIdx.x, ty = threadIdx.y;
    int tid = ty * 32 + tx;

    if (bid < 8192) {                                    // conv x
        size_t i = ((size_t)bid * 256 + tid) * 4;
        float4 v = *(const float4*)(x + i);
        *(__half2*)(xh + i)     = __floats2half2_rn(v.x, v.y);
        *(__half2*)(xh + i + 2) = __floats2half2_rn(v.z, v.w);
        return;
    }
    bid -= 8192;
    if (bid >= 10240) {                                  // bias concat
        int i = (bid - 10240) * 256 + tid;
        float v = (i < 2048) ? bq[i] : (i < 2560 ? bk[i - 2048] : bv[i - 2560]);
        bcat[i] = v;
        return;
    }
    const float* W; __half* T; int N, tilesX;
    if (bid < 4096)      { W = Wq; T = Wcat;             N = DM;  tilesX = 64; }
    else if (bid < 5120) { bid -= 4096; W = Wk; T = Wcat + 2048 * DM; N = KVW; tilesX = 16; }
    else if (bid < 6144) { bid -= 5120; W = Wv; T = Wcat + 2560 * DM; N = KVW; tilesX = 16; }
    else                 { bid -= 6144; W = Wo; T = Woh;              N = DM;  tilesX = 64; }

    __shared__ float t[32][33];
    int bx = (bid % tilesX) * 32;
    int by = (bid / tilesX) * 32;
#pragma unroll
    for (int i = 0; i < 32; i += 8)
        t[ty + i][tx] = W[(size_t)(by + ty + i) * N + bx + tx];
    __syncthreads();
#pragma unroll
    for (int i = 0; i < 32; i += 8)
        T[(size_t)(bx + ty + i) * DM + by + tx] = __float2half_rn(t[tx][ty + i]);
}

// ---------------------------------------------------------------------------
// fp16 GEMM: 128x64 tiles, persistent grid, 3-stage ring, K-chunk 64,
// ONE sync per 64-K. Stage: A 128x(64+8pad) + B 64x(64+8pad) halves = 27648B.
// ---------------------------------------------------------------------------
#define STG_H   13824           // stage size in halves (A 9216 + B 4608)
#define GEMM_SMEM (3 * STG_H * 2)  // 82944 bytes
#define GEMM_GRID 296

__global__ __launch_bounds__(256, 2) void gemm_fp16(
    const __half* __restrict__ Ah, const __half* __restrict__ Bh,
    const float* __restrict__ bias, float* __restrict__ Cf,
    __half* __restrict__ Qh, __half* __restrict__ Kh, __half* __restrict__ Vth,
    int mode, int N, int K, int mTiles, int totTiles)
{
    extern __shared__ __half sm[];
    const int tid = threadIdx.x;
    const int T = K >> 6;                 // 64-K chunks
    const int w = tid >> 5, l = tid & 31;
    const int wm = (w & 3) * 32;
    const int wn = (w >> 2) * 32;
    const int qr = l >> 2, qc = (l & 3) * 2;
    const int arow = (l & 7) + ((l >> 3) & 1) * 8;
    const int acol = (l >> 4) * 8;
    const int brow = (l & 7) + ((l >> 4) & 1) * 8;
    const int bcol = ((l >> 3) & 1) * 8;

    for (int tIdx = blockIdx.x; tIdx < totTiles; tIdx += gridDim.x) {
        const int bm = (tIdx % mTiles) * 128;
        const int bn = (tIdx / mTiles) * 64;

        auto load_stage = [&](int s, int k0) {
            __half* base = sm + s * STG_H;
            // A: 128 rows x 64 halves (8 cp16/row) = 1024 slots
#pragma unroll
            for (int t = 0; t < 4; t++) {
                int c = tid + t * 256;
                int row = c >> 3, seg = (c & 7) * 8;
                cp16(base + row * 72 + seg,
                     Ah + (size_t)(bm + row) * K + k0 + seg);
            }
            // B: 64 rows x 64 halves = 512 slots
#pragma unroll
            for (int t = 0; t < 2; t++) {
                int c = tid + t * 256;
                int row = c >> 3, seg = (c & 7) * 8;
                cp16(base + 9216 + row * 72 + seg,
                     Bh + (size_t)(bn + row) * K + k0 + seg);
            }
        };

        float acc[2][4][4];
#pragma unroll
        for (int mi = 0; mi < 2; mi++)
#pragma unroll
            for (int ni = 0; ni < 4; ni++)
#pragma unroll
                for (int r = 0; r < 4; r++) acc[mi][ni][r] = 0.f;

        load_stage(0, 0);  CP_COMMIT();
        load_stage(1, 64); CP_COMMIT();

        int sIdx = 0;
        for (int i = 0; i < T; i++) {
            if (i < T - 1) CP_WAIT(1);
            else           CP_WAIT(0);
            __syncthreads();
            if (i + 2 < T) {   // refill stage (i+2)%3 == (i-1)%3
                int ls = sIdx + 2; if (ls >= 3) ls -= 3;
                load_stage(ls, (i + 2) * 64);
                CP_COMMIT();
            }

            const __half* Ahs = sm + sIdx * STG_H;
            const __half* Bhs = Ahs + 9216;

#pragma unroll
            for (int ks = 0; ks < 64; ks += 16) {
                unsigned ah[2][4];
#pragma unroll
                for (int mi = 0; mi < 2; mi++)
                    ldsm_x4(ah[mi], Ahs + (wm + mi * 16 + arow) * 72 + ks + acol);
#pragma unroll
                for (int p = 0; p < 2; p++) {
                    unsigned bh[4];
                    ldsm_x4(bh, Bhs + (wn + p * 16 + brow) * 72 + ks + bcol);
#pragma unroll
                    for (int mi = 0; mi < 2; mi++) {
                        mma16816(acc[mi][2 * p],     ah[mi], bh);
                        mma16816(acc[mi][2 * p + 1], ah[mi], bh + 2);
                    }
                }
            }
            if (++sIdx == 3) sIdx = 0;
        }

#pragma unroll
        for (int mi = 0; mi < 2; mi++) {
#pragma unroll
            for (int ni = 0; ni < 4; ni++) {
                int r  = bm + wm + mi * 16 + qr;
                int cc = bn + wn + ni * 8 + qc;
                float b0 = bias[cc], b1 = bias[cc + 1];
                float v0 = acc[mi][ni][0] + b0, v1 = acc[mi][ni][1] + b1;
                float v2 = acc[mi][ni][2] + b0, v3 = acc[mi][ni][3] + b1;
                if (mode == 0) {
                    *(float2*)(Cf + (size_t)r * N + cc)       = make_float2(v0, v1);
                    *(float2*)(Cf + (size_t)(r + 8) * N + cc) = make_float2(v2, v3);
                } else if (cc < 2048) {             // Q
                    *(unsigned*)(Qh + (size_t)r * DM + cc)       = pack2h(v0, v1);
                    *(unsigned*)(Qh + (size_t)(r + 8) * DM + cc) = pack2h(v2, v3);
                } else if (cc < 2560) {             // K
                    int col = cc - 2048;
                    *(unsigned*)(Kh + (size_t)r * KVW + col)       = pack2h(v0, v1);
                    *(unsigned*)(Kh + (size_t)(r + 8) * KVW + col) = pack2h(v2, v3);
                } else {                            // V transposed [b][dk][s]
                    int col = cc - 2560;
                    int bb = r >> 11, sl = r & (S_LEN - 1);
                    size_t base = ((size_t)bb * KVW + col) * S_LEN;
                    Vth[base + sl]             = __float2half_rn(v0);
                    Vth[base + S_LEN + sl]     = __float2half_rn(v1);
                    Vth[base + sl + 8]         = __float2half_rn(v2);
                    Vth[base + S_LEN + sl + 8] = __float2half_rn(v3);
                }
            }
        }
        __syncthreads();   // protect stage buffers before next tile's prologue
    }
}

// ---------------------------------------------------------------------------
// fp16 flash attention (causal, GQA), hi-only, exp2 softmax.
// 3-stage K/V ring, ONE sync per kv tile. (unchanged from R14)
// ---------------------------------------------------------------------------
#define FL_SMEM ((9216 + 3 * 9216) * 2)   // 73728 bytes

__global__ __launch_bounds__(256) void gqa_flash_fp16(
    const __half* __restrict__ Qh_g, const __half* __restrict__ Kh_g,
    const __half* __restrict__ Vth_g, __half* __restrict__ Ch_g)
{
    extern __shared__ __half sb[];
    const int tid = threadIdx.x;
    const int w = tid >> 5, l = tid & 31;
    const int qr = l >> 2, qc = (l & 3) * 2;
    const int arow = (l & 7) + ((l >> 3) & 1) * 8;
    const int acol = (l >> 4) * 8;
    const int brow = (l & 7) + ((l >> 4) & 1) * 8;
    const int bcol = ((l >> 3) & 1) * 8;
    const int mtile = (gridDim.x - 1) - blockIdx.x;   // big blocks first
    const int h = blockIdx.y, b = blockIdx.z;
    const int kvh = h >> 2;
    const int m0 = mtile * 128;
    const int kvTiles = 2 * mtile + 2;
    const int lastTile = 2 * mtile + (w >> 2);

    const __half* Qph = Qh_g + ((size_t)(b * S_LEN + m0)) * DM + h * 64;
#pragma unroll
    for (int t = 0; t < 4; t++) {
        int idx = tid + t * 256;
        int row = idx >> 3, seg = (idx & 7) * 8;
        cp16(sb + row * 72 + seg, Qph + (size_t)row * DM + seg);
    }

    auto load_kv = [&](int sidx, int jt) {
        __half* st = sb + 9216 + sidx * 9216;
        const int k0 = jt * 64;
        const __half* Kg = Kh_g + ((size_t)(b * S_LEN + k0)) * KVW + kvh * 64;
        const __half* Vg = Vth_g + ((size_t)b * KVW + kvh * 64) * S_LEN + k0;
#pragma unroll
        for (int t = 0; t < 2; t++) {
            int idx = tid + t * 256;
            int row = idx >> 3, seg = (idx & 7) * 8;
            cp16(st + row * 72 + seg,        Kg + (size_t)row * KVW + seg);
            cp16(st + 4608 + row * 72 + seg, Vg + (size_t)row * S_LEN + seg);
        }
    };

    load_kv(0, 0); CP_COMMIT();
    load_kv(1, 1); CP_COMMIT();

    unsigned aqh[4][4];
    float o[8][4];
#pragma unroll
    for (int n = 0; n < 8; n++)
#pragma unroll
        for (int r = 0; r < 4; r++) o[n][r] = 0.f;
    float mrow0 = -INFINITY, mrow1 = -INFINITY, lrow0 = 0.f, lrow1 = 0.f;

    const int r0 = m0 + w * 16 + qr;
    const int r1 = r0 + 8;

    int sIdx = 0;
    for (int jt = 0; jt < kvTiles; jt++) {
        if (jt < kvTiles - 1) CP_WAIT(1);
        else                  CP_WAIT(0);
        __syncthreads();
        if (jt + 2 < kvTiles) {
            int ls = sIdx + 2; if (ls >= 3) ls -= 3;
            load_kv(ls, jt + 2);
            CP_COMMIT();
        }
        if (jt == 0) {
#pragma unroll
            for (int j = 0; j < 4; j++)
                ldsm_x4(aqh[j], sb + (w * 16 + arow) * 72 + j * 16 + acol);
        }
        const __half* st = sb + 9216 + sIdx * 9216;

        if (jt <= lastTile) {
            const int k0 = jt * 64;
            float s[8][4];
#pragma unroll
            for (int n = 0; n < 8; n++)
#pragma unroll
                for (int r = 0; r < 4; r++) s[n][r] = 0.f;

#pragma unroll
            for (int j = 0; j < 4; j++) {
#pragma unroll
                for (int p = 0; p < 4; p++) {
                    unsigned bh[4];
                    ldsm_x4(bh, st + (p * 16 + brow) * 72 + j * 16 + bcol);
                    mma16816(s[2 * p],     aqh[j], bh);
                    mma16816(s[2 * p + 1], aqh[j], bh + 2);
                }
            }

            const float rs = 0.18033688f;   // log2(e)/8
            if (k0 + 63 > m0 + w * 16) {
#pragma unroll
                for (int n = 0; n < 8; n++) {
                    int c0 = k0 + n * 8 + qc;
                    s[n][0] = (c0     > r0) ? -1e30f : s[n][0] * rs;
                    s[n][1] = (c0 + 1 > r0) ? -1e30f : s[n][1] * rs;
                    s[n][2] = (c0     > r1) ? -1e30f : s[n][2] * rs;
                    s[n][3] = (c0 + 1 > r1) ? -1e30f : s[n][3] * rs;
                }
            } else {
#pragma unroll
                for (int n = 0; n < 8; n++)
#pragma unroll
                    for (int r = 0; r < 4; r++) s[n][r] *= rs;
            }

            float mx0 = -1e30f, mx1 = -1e30f;
#pragma unroll
            for (int n = 0; n < 8; n++) {
                mx0 = fmaxf(mx0, fmaxf(s[n][0], s[n][1]));
                mx1 = fmaxf(mx1, fmaxf(s[n][2], s[n][3]));
            }
            mx0 = fmaxf(mx0, __shfl_xor_sync(0xffffffffu, mx0, 1));
            mx0 = fmaxf(mx0, __shfl_xor_sync(0xffffffffu, mx0, 2));
            mx1 = fmaxf(mx1, __shfl_xor_sync(0xffffffffu, mx1, 1));
            mx1 = fmaxf(mx1, __shfl_xor_sync(0xffffffffu, mx1, 2));
            float mn0 = fmaxf(mrow0, mx0), mn1 = fmaxf(mrow1, mx1);
            float cr0 = exp2f(mrow0 - mn0), cr1 = exp2f(mrow1 - mn1);
            float sum0 = 0.f, sum1 = 0.f;
#pragma unroll
            for (int n = 0; n < 8; n++) {
                s[n][0] = exp2f(s[n][0] - mn0);
                s[n][1] = exp2f(s[n][1] - mn0);
                s[n][2] = exp2f(s[n][2] - mn1);
                s[n][3] = exp2f(s[n][3] - mn1);
                sum0 += s[n][0] + s[n][1];
                sum1 += s[n][2] + s[n][3];
            }
            sum0 += __shfl_xor_sync(0xffffffffu, sum0, 1);
            sum0 += __shfl_xor_sync(0xffffffffu, sum0, 2);
            sum1 += __shfl_xor_sync(0xffffffffu, sum1, 1);
            sum1 += __shfl_xor_sync(0xffffffffu, sum1, 2);
            lrow0 = lrow0 * cr0 + sum0;
            lrow1 = lrow1 * cr1 + sum1;
            mrow0 = mn0; mrow1 = mn1;
#pragma unroll
            for (int n = 0; n < 8; n++) {
                o[n][0] *= cr0; o[n][1] *= cr0;
                o[n][2] *= cr1; o[n][3] *= cr1;
            }

            unsigned pah[4][4];
#pragma unroll
            for (int j = 0; j < 4; j++) {
                pah[j][0] = pack2h(s[2 * j][0],     s[2 * j][1]);
                pah[j][1] = pack2h(s[2 * j][2],     s[2 * j][3]);
                pah[j][2] = pack2h(s[2 * j + 1][0], s[2 * j + 1][1]);
                pah[j][3] = pack2h(s[2 * j + 1][2], s[2 * j + 1][3]);
            }

#pragma unroll
            for (int j = 0; j < 4; j++) {
#pragma unroll
                for (int p = 0; p < 4; p++) {
                    unsigned bh[4];
                    ldsm_x4(bh, st + 4608 + (p * 16 + brow) * 72 + j * 16 + bcol);
                    mma16816(o[2 * p],     pah[j], bh);
                    mma16816(o[2 * p + 1], pah[j], bh + 2);
                }
            }
        }
        if (++sIdx == 3) sIdx = 0;
    }

    float inv0 = 1.f / lrow0, inv1 = 1.f / lrow1;
    size_t base0 = ((size_t)(b * S_LEN) + r0) * DM + h * 64;
    size_t base1 = ((size_t)(b * S_LEN) + r1) * DM + h * 64;
#pragma unroll
    for (int n = 0; n < 8; n++) {
        *(__half2*)(Ch_g + base0 + n * 8 + qc) = __floats2half2_rn(o[n][0] * inv0, o[n][1] * inv0);
        *(__half2*)(Ch_g + base1 + n * 8 + qc) = __floats2half2_rn(o[n][2] * inv1, o[n][3] * inv1);
    }
}

// ---------------------------------------------------------------------------
extern "C" void kernel_launch(void* const* d_in, const int* in_sizes, int n_in,
                              void* d_out, int out_size)
{
    (void)in_sizes; (void)n_in; (void)out_size;
    const float* x  = (const float*)d_in[0];
    const float* Wq = (const float*)d_in[2];
    const float* bq = (const float*)d_in[3];
    const float* Wk = (const float*)d_in[4];
    const float* bk = (const float*)d_in[5];
    const float* Wv = (const float*)d_in[6];
    const float* bv = (const float*)d_in[7];
    const float* Wo = (const float*)d_in[8];
    const float* bo = (const float*)d_in[9];
    float* out = (float*)d_out;

    __half *xh, *Qh, *Kh, *Vth, *Ch, *Wcat, *Woh;
    float* bcat;
    cudaGetSymbolAddress((void**)&xh, g_xh);
    cudaGetSymbolAddress((void**)&Qh, g_Qh);
    cudaGetSymbolAddress((void**)&Kh, g_Kh);
    cudaGetSymbolAddress((void**)&Vth, g_Vth);
    cudaGetSymbolAddress((void**)&Ch, g_Ch);
    cudaGetSymbolAddress((void**)&Wcat, g_Wcat);
    cudaGetSymbolAddress((void**)&Woh, g_Woh);
    cudaGetSymbolAddress((void**)&bcat, g_bcat);

    cudaFuncSetAttribute(gemm_fp16,
                         cudaFuncAttributeMaxDynamicSharedMemorySize, GEMM_SMEM);
    cudaFuncSetAttribute(gqa_flash_fp16,
                         cudaFuncAttributeMaxDynamicSharedMemorySize, FL_SMEM);

    // fused prep
    prep_all<<<PREP_BLOCKS, dim3(32, 8)>>>(x, Wq, Wk, Wv, Wo, bq, bk, bv,
                                           xh, Wcat, Woh, bcat);

    // fused QKV projection: tiles 128x64 -> 32 x 48 = 1536
    gemm_fp16<<<GEMM_GRID, 256, GEMM_SMEM>>>(
        xh, Wcat, bcat, nullptr, Qh, Kh, Vth, 1, NCAT, DM, 32, 1536);

    // attention
    gqa_flash_fp16<<<dim3(S_LEN / 128, NH, B_SZ), 256, FL_SMEM>>>(
        Qh, Kh, Vth, Ch);

    // output projection: tiles 128x64 -> 32 x 32 = 1024
    gemm_fp16<<<GEMM_GRID, 256, GEMM_SMEM>>>(
        Ch, Woh, bo, out, nullptr, nullptr, nullptr, 0, DM, DM, 32, 1024);
}

// round 16
// speedup vs baseline: 1.1485x; 1.0091x over previous
#include <cuda_runtime.h>
#include <cuda_fp16.h>
#include <cstdint>
#include <math.h>

#define B_SZ   2
#define S_LEN  2048
#define DM     2048
#define NH     32
#define NKV    8
#define DK     64
#define KVW    (NKV * DK)      // 512
#define MROWS  (B_SZ * S_LEN)  // 4096
#define NCAT   3072            // Q(2048) + K(512) + V(512)

// ---------------- scratch ----------------
__device__ __half g_xh[MROWS * DM];
__device__ __half g_Qh[MROWS * DM];
__device__ __half g_Kh[MROWS * KVW];
__device__ __half g_Vth[B_SZ * KVW * S_LEN];      // [b][dk][s]
__device__ __half g_Ch[MROWS * DM];
__device__ __half g_Wcat[NCAT * DM];              // [N][K] concat Q|K|V weights (hi)
__device__ __half g_Woh[DM * DM];
__device__ float  g_bcat[NCAT];

// ---------------- helpers ----------------
__device__ __forceinline__ void cp16(void* s, const void* g) {
    unsigned sa = (unsigned)__cvta_generic_to_shared(s);
    asm volatile("cp.async.cg.shared.global [%0], [%1], 16;\n" :: "r"(sa), "l"(g));
}
#define CP_COMMIT() asm volatile("cp.async.commit_group;\n")
#define CP_WAIT(n)  asm volatile("cp.async.wait_group %0;\n" :: "n"(n) : "memory")

__device__ __forceinline__ void mma16816(float* c, const unsigned* a, const unsigned* b) {
    asm volatile(
        "mma.sync.aligned.m16n8k16.row.col.f32.f16.f16.f32 "
        "{%0,%1,%2,%3}, {%4,%5,%6,%7}, {%8,%9}, {%0,%1,%2,%3};\n"
        : "+f"(c[0]), "+f"(c[1]), "+f"(c[2]), "+f"(c[3])
        : "r"(a[0]), "r"(a[1]), "r"(a[2]), "r"(a[3]), "r"(b[0]), "r"(b[1]));
}
__device__ __forceinline__ void ldsm_x4(unsigned* r, const void* p) {
    unsigned a = (unsigned)__cvta_generic_to_shared(p);
    asm volatile("ldmatrix.sync.aligned.m8n8.x4.shared.b16 {%0,%1,%2,%3}, [%4];\n"
                 : "=r"(r[0]), "=r"(r[1]), "=r"(r[2]), "=r"(r[3]) : "r"(a));
}
__device__ __forceinline__ unsigned pack2h(float v0, float v1) {
    __half2 h = __floats2half2_rn(v0, v1);
    return *(unsigned*)&h;
}
// guaranteed single-MUFU exp2
__device__ __forceinline__ float ex2f(float x) {
    float y;
    asm("ex2.approx.ftz.f32 %0, %1;" : "=f"(y) : "f"(x));
    return y;
}

// ---------------------------------------------------------------------------
// fused prep (one launch)
// ---------------------------------------------------------------------------
#define PREP_BLOCKS 18444

__global__ void prep_all(const float* __restrict__ x,
                         const float* __restrict__ Wq, const float* __restrict__ Wk,
                         const float* __restrict__ Wv, const float* __restrict__ Wo,
                         const float* __restrict__ bq, const float* __restrict__ bk,
                         const float* __restrict__ bv,
                         __half* __restrict__ xh, __half* __restrict__ Wcat,
                         __half* __restrict__ Woh, float* __restrict__ bcat)
{
    int bid = blockIdx.x;
    int tx = threadIdx.x, ty = threadIdx.y;
    int tid = ty * 32 + tx;

    if (bid < 8192) {                                    // conv x
        size_t i = ((size_t)bid * 256 + tid) * 4;
        float4 v = *(const float4*)(x + i);
        *(__half2*)(xh + i)     = __floats2half2_rn(v.x, v.y);
        *(__half2*)(xh + i + 2) = __floats2half2_rn(v.z, v.w);
        return;
    }
    bid -= 8192;
    if (bid >= 10240) {                                  // bias concat
        int i = (bid - 10240) * 256 + tid;
        float v = (i < 2048) ? bq[i] : (i < 2560 ? bk[i - 2048] : bv[i - 2560]);
        bcat[i] = v;
        return;
    }
    const float* W; __half* T; int N, tilesX;
    if (bid < 4096)      { W = Wq; T = Wcat;             N = DM;  tilesX = 64; }
    else if (bid < 5120) { bid -= 4096; W = Wk; T = Wcat + 2048 * DM; N = KVW; tilesX = 16; }
    else if (bid < 6144) { bid -= 5120; W = Wv; T = Wcat + 2560 * DM; N = KVW; tilesX = 16; }
    else                 { bid -= 6144; W = Wo; T = Woh;              N = DM;  tilesX = 64; }

    __shared__ float t[32][33];
    int bx = (bid % tilesX) * 32;
    int by = (bid / tilesX) * 32;
#pragma unroll
    for (int i = 0; i < 32; i += 8)
        t[ty + i][tx] = W[(size_t)(by + ty + i) * N + bx + tx];
    __syncthreads();
#pragma unroll
    for (int i = 0; i < 32; i += 8)
        T[(size_t)(bx + ty + i) * DM + by + tx] = __float2half_rn(t[tx][ty + i]);
}

// ---------------------------------------------------------------------------
// fp16 GEMM: 128x64 tiles, persistent grid, 3-stage ring, K-chunk 64,
// ONE sync per 64-K. (unchanged from R15)
// ---------------------------------------------------------------------------
#define STG_H   13824
#define GEMM_SMEM (3 * STG_H * 2)  // 82944 bytes
#define GEMM_GRID 296

__global__ __launch_bounds__(256, 2) void gemm_fp16(
    const __half* __restrict__ Ah, const __half* __restrict__ Bh,
    const float* __restrict__ bias, float* __restrict__ Cf,
    __half* __restrict__ Qh, __half* __restrict__ Kh, __half* __restrict__ Vth,
    int mode, int N, int K, int mTiles, int totTiles)
{
    extern __shared__ __half sm[];
    const int tid = threadIdx.x;
    const int T = K >> 6;
    const int w = tid >> 5, l = tid & 31;
    const int wm = (w & 3) * 32;
    const int wn = (w >> 2) * 32;
    const int qr = l >> 2, qc = (l & 3) * 2;
    const int arow = (l & 7) + ((l >> 3) & 1) * 8;
    const int acol = (l >> 4) * 8;
    const int brow = (l & 7) + ((l >> 4) & 1) * 8;
    const int bcol = ((l >> 3) & 1) * 8;

    for (int tIdx = blockIdx.x; tIdx < totTiles; tIdx += gridDim.x) {
        const int bm = (tIdx % mTiles) * 128;
        const int bn = (tIdx / mTiles) * 64;

        auto load_stage = [&](int s, int k0) {
            __half* base = sm + s * STG_H;
#pragma unroll
            for (int t = 0; t < 4; t++) {
                int c = tid + t * 256;
                int row = c >> 3, seg = (c & 7) * 8;
                cp16(base + row * 72 + seg,
                     Ah + (size_t)(bm + row) * K + k0 + seg);
            }
#pragma unroll
            for (int t = 0; t < 2; t++) {
                int c = tid + t * 256;
                int row = c >> 3, seg = (c & 7) * 8;
                cp16(base + 9216 + row * 72 + seg,
                     Bh + (size_t)(bn + row) * K + k0 + seg);
            }
        };

        float acc[2][4][4];
#pragma unroll
        for (int mi = 0; mi < 2; mi++)
#pragma unroll
            for (int ni = 0; ni < 4; ni++)
#pragma unroll
                for (int r = 0; r < 4; r++) acc[mi][ni][r] = 0.f;

        load_stage(0, 0);  CP_COMMIT();
        load_stage(1, 64); CP_COMMIT();

        int sIdx = 0;
        for (int i = 0; i < T; i++) {
            if (i < T - 1) CP_WAIT(1);
            else           CP_WAIT(0);
            __syncthreads();
            if (i + 2 < T) {
                int ls = sIdx + 2; if (ls >= 3) ls -= 3;
                load_stage(ls, (i + 2) * 64);
                CP_COMMIT();
            }

            const __half* Ahs = sm + sIdx * STG_H;
            const __half* Bhs = Ahs + 9216;

#pragma unroll
            for (int ks = 0; ks < 64; ks += 16) {
                unsigned ah[2][4];
#pragma unroll
                for (int mi = 0; mi < 2; mi++)
                    ldsm_x4(ah[mi], Ahs + (wm + mi * 16 + arow) * 72 + ks + acol);
#pragma unroll
                for (int p = 0; p < 2; p++) {
                    unsigned bh[4];
                    ldsm_x4(bh, Bhs + (wn + p * 16 + brow) * 72 + ks + bcol);
#pragma unroll
                    for (int mi = 0; mi < 2; mi++) {
                        mma16816(acc[mi][2 * p],     ah[mi], bh);
                        mma16816(acc[mi][2 * p + 1], ah[mi], bh + 2);
                    }
                }
            }
            if (++sIdx == 3) sIdx = 0;
        }

#pragma unroll
        for (int mi = 0; mi < 2; mi++) {
#pragma unroll
            for (int ni = 0; ni < 4; ni++) {
                int r  = bm + wm + mi * 16 + qr;
                int cc = bn + wn + ni * 8 + qc;
                float b0 = bias[cc], b1 = bias[cc + 1];
                float v0 = acc[mi][ni][0] + b0, v1 = acc[mi][ni][1] + b1;
                float v2 = acc[mi][ni][2] + b0, v3 = acc[mi][ni][3] + b1;
                if (mode == 0) {
                    *(float2*)(Cf + (size_t)r * N + cc)       = make_float2(v0, v1);
                    *(float2*)(Cf + (size_t)(r + 8) * N + cc) = make_float2(v2, v3);
                } else if (cc < 2048) {             // Q
                    *(unsigned*)(Qh + (size_t)r * DM + cc)       = pack2h(v0, v1);
                    *(unsigned*)(Qh + (size_t)(r + 8) * DM + cc) = pack2h(v2, v3);
                } else if (cc < 2560) {             // K
                    int col = cc - 2048;
                    *(unsigned*)(Kh + (size_t)r * KVW + col)       = pack2h(v0, v1);
                    *(unsigned*)(Kh + (size_t)(r + 8) * KVW + col) = pack2h(v2, v3);
                } else {                            // V transposed [b][dk][s]
                    int col = cc - 2560;
                    int bb = r >> 11, sl = r & (S_LEN - 1);
                    size_t base = ((size_t)bb * KVW + col) * S_LEN;
                    Vth[base + sl]             = __float2half_rn(v0);
                    Vth[base + S_LEN + sl]     = __float2half_rn(v1);
                    Vth[base + sl + 8]         = __float2half_rn(v2);
                    Vth[base + S_LEN + sl + 8] = __float2half_rn(v3);
                }
            }
        }
        __syncthreads();
    }
}

// ---------------------------------------------------------------------------
// fp16 flash attention (causal, GQA), hi-only, HW-ex2 softmax.
// __launch_bounds__(256,2) forces regs<=128 -> 2 CTAs/SM guaranteed.
// 3-stage K/V ring, ONE sync per kv tile.
// ---------------------------------------------------------------------------
#define FL_SMEM ((9216 + 3 * 9216) * 2)   // 73728 bytes

__global__ __launch_bounds__(256, 2) void gqa_flash_fp16(
    const __half* __restrict__ Qh_g, const __half* __restrict__ Kh_g,
    const __half* __restrict__ Vth_g, __half* __restrict__ Ch_g)
{
    extern __shared__ __half sb[];
    const int tid = threadIdx.x;
    const int w = tid >> 5, l = tid & 31;
    const int qr = l >> 2, qc = (l & 3) * 2;
    const int arow = (l & 7) + ((l >> 3) & 1) * 8;
    const int acol = (l >> 4) * 8;
    const int brow = (l & 7) + ((l >> 4) & 1) * 8;
    const int bcol = ((l >> 3) & 1) * 8;
    const int mtile = (gridDim.x - 1) - blockIdx.x;   // big blocks first
    const int h = blockIdx.y, b = blockIdx.z;
    const int kvh = h >> 2;
    const int m0 = mtile * 128;
    const int kvTiles = 2 * mtile + 2;
    const int lastTile = 2 * mtile + (w >> 2);

    const __half* Qph = Qh_g + ((size_t)(b * S_LEN + m0)) * DM + h * 64;
#pragma unroll
    for (int t = 0; t < 4; t++) {
        int idx = tid + t * 256;
        int row = idx >> 3, seg = (idx & 7) * 8;
        cp16(sb + row * 72 + seg, Qph + (size_t)row * DM + seg);
    }

    auto load_kv = [&](int sidx, int jt) {
        __half* st = sb + 9216 + sidx * 9216;
        const int k0 = jt * 64;
        const __half* Kg = Kh_g + ((size_t)(b * S_LEN + k0)) * KVW + kvh * 64;
        const __half* Vg = Vth_g + ((size_t)b * KVW + kvh * 64) * S_LEN + k0;
#pragma unroll
        for (int t = 0; t < 2; t++) {
            int idx = tid + t * 256;
            int row = idx >> 3, seg = (idx & 7) * 8;
            cp16(st + row * 72 + seg,        Kg + (size_t)row * KVW + seg);
            cp16(st + 4608 + row * 72 + seg, Vg + (size_t)row * S_LEN + seg);
        }
    };

    load_kv(0, 0); CP_COMMIT();
    load_kv(1, 1); CP_COMMIT();

    unsigned aqh[4][4];
    float o[8][4];
#pragma unroll
    for (int n = 0; n < 8; n++)
#pragma unroll
        for (int r = 0; r < 4; r++) o[n][r] = 0.f;
    float mrow0 = -INFINITY, mrow1 = -INFINITY, lrow0 = 0.f, lrow1 = 0.f;

    const int r0 = m0 + w * 16 + qr;
    const int r1 = r0 + 8;

    int sIdx = 0;
    for (int jt = 0; jt < kvTiles; jt++) {
        if (jt < kvTiles - 1) CP_WAIT(1);
        else                  CP_WAIT(0);
        __syncthreads();
        if (jt + 2 < kvTiles) {
            int ls = sIdx + 2; if (ls >= 3) ls -= 3;
            load_kv(ls, jt + 2);
            CP_COMMIT();
        }
        if (jt == 0) {
#pragma unroll
            for (int j = 0; j < 4; j++)
                ldsm_x4(aqh[j], sb + (w * 16 + arow) * 72 + j * 16 + acol);
        }
        const __half* st = sb + 9216 + sIdx * 9216;

        if (jt <= lastTile) {
            const int k0 = jt * 64;
            float s[8][4];
#pragma unroll
            for (int n = 0; n < 8; n++)
#pragma unroll
                for (int r = 0; r < 4; r++) s[n][r] = 0.f;

#pragma unroll
            for (int j = 0; j < 4; j++) {
#pragma unroll
                for (int p = 0; p < 4; p++) {
                    unsigned bh[4];
                    ldsm_x4(bh, st + (p * 16 + brow) * 72 + j * 16 + bcol);
                    mma16816(s[2 * p],     aqh[j], bh);
                    mma16816(s[2 * p + 1], aqh[j], bh + 2);
                }
            }

            const float rs = 0.18033688f;   // log2(e)/8
            if (k0 + 63 > m0 + w * 16) {
#pragma unroll
                for (int n = 0; n < 8; n++) {
                    int c0 = k0 + n * 8 + qc;
                    s[n][0] = (c0     > r0) ? -1e30f : s[n][0] * rs;
                    s[n][1] = (c0 + 1 > r0) ? -1e30f : s[n][1] * rs;
                    s[n][2] = (c0     > r1) ? -1e30f : s[n][2] * rs;
                    s[n][3] = (c0 + 1 > r1) ? -1e30f : s[n][3] * rs;
                }
            } else {
#pragma unroll
                for (int n = 0; n < 8; n++)
#pragma unroll
                    for (int r = 0; r < 4; r++) s[n][r] *= rs;
            }

            float mx0 = -1e30f, mx1 = -1e30f;
#pragma unroll
            for (int n = 0; n < 8; n++) {
                mx0 = fmaxf(mx0, fmaxf(s[n][0], s[n][1]));
                mx1 = fmaxf(mx1, fmaxf(s[n][2], s[n][3]));
            }
            mx0 = fmaxf(mx0, __shfl_xor_sync(0xffffffffu, mx0, 1));
            mx0 = fmaxf(mx0, __shfl_xor_sync(0xffffffffu, mx0, 2));
            mx1 = fmaxf(mx1, __shfl_xor_sync(0xffffffffu, mx1, 1));
            mx1 = fmaxf(mx1, __shfl_xor_sync(0xffffffffu, mx1, 2));
            float mn0 = fmaxf(mrow0, mx0), mn1 = fmaxf(mrow1, mx1);
            float cr0 = ex2f(mrow0 - mn0), cr1 = ex2f(mrow1 - mn1);
            float sum0 = 0.f, sum1 = 0.f;
#pragma unroll
            for (int n = 0; n < 8; n++) {
                s[n][0] = ex2f(s[n][0] - mn0);
                s[n][1] = ex2f(s[n][1] - mn0);
                s[n][2] = ex2f(s[n][2] - mn1);
                s[n][3] = ex2f(s[n][3] - mn1);
                sum0 += s[n][0] + s[n][1];
                sum1 += s[n][2] + s[n][3];
            }
            sum0 += __shfl_xor_sync(0xffffffffu, sum0, 1);
            sum0 += __shfl_xor_sync(0xffffffffu, sum0, 2);
            sum1 += __shfl_xor_sync(0xffffffffu, sum1, 1);
            sum1 += __shfl_xor_sync(0xffffffffu, sum1, 2);
            lrow0 = lrow0 * cr0 + sum0;
            lrow1 = lrow1 * cr1 + sum1;
            mrow0 = mn0; mrow1 = mn1;
#pragma unroll
            for (int n = 0; n < 8; n++) {
                o[n][0] *= cr0; o[n][1] *= cr0;
                o[n][2] *= cr1; o[n][3] *= cr1;
            }

            unsigned pah[4][4];
#pragma unroll
            for (int j = 0; j < 4; j++) {
                pah[j][0] = pack2h(s[2 * j][0],     s[2 * j][1]);
                pah[j][1] = pack2h(s[2 * j][2],     s[2 * j][3]);
                pah[j][2] = pack2h(s[2 * j + 1][0], s[2 * j + 1][1]);
                pah[j][3] = pack2h(s[2 * j + 1][2], s[2 * j + 1][3]);
            }

#pragma unroll
            for (int j = 0; j < 4; j++) {
#pragma unroll
                for (int p = 0; p < 4; p++) {
                    unsigned bh[4];
                    ldsm_x4(bh, st + 4608 + (p * 16 + brow) * 72 + j * 16 + bcol);
                    mma16816(o[2 * p],     pah[j], bh);
                    mma16816(o[2 * p + 1], pah[j], bh + 2);
                }
            }
        }
        if (++sIdx == 3) sIdx = 0;
    }

    float inv0 = 1.f / lrow0, inv1 = 1.f / lrow1;
    size_t base0 = ((size_t)(b * S_LEN) + r0) * DM + h * 64;
    size_t base1 = ((size_t)(b * S_LEN) + r1) * DM + h * 64;
#pragma unroll
    for (int n = 0; n < 8; n++) {
        *(__half2*)(Ch_g + base0 + n * 8 + qc) = __floats2half2_rn(o[n][0] * inv0, o[n][1] * inv0);
        *(__half2*)(Ch_g + base1 + n * 8 + qc) = __floats2half2_rn(o[n][2] * inv1, o[n][3] * inv1);
    }
}

// ---------------------------------------------------------------------------
extern "C" void kernel_launch(void* const* d_in, const int* in_sizes, int n_in,
                              void* d_out, int out_size)
{
    (void)in_sizes; (void)n_in; (void)out_size;
    const float* x  = (const float*)d_in[0];
    const float* Wq = (const float*)d_in[2];
    const float* bq = (const float*)d_in[3];
    const float* Wk = (const float*)d_in[4];
    const float* bk = (const float*)d_in[5];
    const float* Wv = (const float*)d_in[6];
    const float* bv = (const float*)d_in[7];
    const float* Wo = (const float*)d_in[8];
    const float* bo = (const float*)d_in[9];
    float* out = (float*)d_out;

    __half *xh, *Qh, *Kh, *Vth, *Ch, *Wcat, *Woh;
    float* bcat;
    cudaGetSymbolAddress((void**)&xh, g_xh);
    cudaGetSymbolAddress((void**)&Qh, g_Qh);
    cudaGetSymbolAddress((void**)&Kh, g_Kh);
    cudaGetSymbolAddress((void**)&Vth, g_Vth);
    cudaGetSymbolAddress((void**)&Ch, g_Ch);
    cudaGetSymbolAddress((void**)&Wcat, g_Wcat);
    cudaGetSymbolAddress((void**)&Woh, g_Woh);
    cudaGetSymbolAddress((void**)&bcat, g_bcat);

    cudaFuncSetAttribute(gemm_fp16,
                         cudaFuncAttributeMaxDynamicSharedMemorySize, GEMM_SMEM);
    cudaFuncSetAttribute(gqa_flash_fp16,
                         cudaFuncAttributeMaxDynamicSharedMemorySize, FL_SMEM);

    // fused prep
    prep_all<<<PREP_BLOCKS, dim3(32, 8)>>>(x, Wq, Wk, Wv, Wo, bq, bk, bv,
                                           xh, Wcat, Woh, bcat);

    // fused QKV projection: tiles 128x64 -> 32 x 48 = 1536
    gemm_fp16<<<GEMM_GRID, 256, GEMM_SMEM>>>(
        xh, Wcat, bcat, nullptr, Qh, Kh, Vth, 1, NCAT, DM, 32, 1536);

    // attention
    gqa_flash_fp16<<<dim3(S_LEN / 128, NH, B_SZ), 256, FL_SMEM>>>(
        Qh, Kh, Vth, Ch);

    // output projection: tiles 128x64 -> 32 x 32 = 1024
    gemm_fp16<<<GEMM_GRID, 256, GEMM_SMEM>>>(
        Ch, Woh, bo, out, nullptr, nullptr, nullptr, 0, DM, DM, 32, 1024);
}

// round 17
// speedup vs baseline: 1.1533x; 1.0042x over previous
#include <cuda_runtime.h>
#include <cuda_fp16.h>
#include <cstdint>
#include <math.h>

#define B_SZ   2
#define S_LEN  2048
#define DM     2048
#define NH     32
#define NKV    8
#define DK     64
#define KVW    (NKV * DK)      // 512
#define MROWS  (B_SZ * S_LEN)  // 4096
#define NCAT   3072            // Q(2048) + K(512) + V(512)

// ---------------- scratch ----------------
__device__ __half g_xh[MROWS * DM];
__device__ __half g_Qh[MROWS * DM];
__device__ __half g_Kh[MROWS * KVW];
__device__ __half g_Vth[B_SZ * KVW * S_LEN];      // [b][dk][s]
__device__ __half g_Ch[MROWS * DM];
__device__ __half g_Wcat[NCAT * DM];              // [N][K] concat Q|K|V weights (hi)
__device__ __half g_Woh[DM * DM];
__device__ float  g_bcat[NCAT];

// ---------------- helpers ----------------
__device__ __forceinline__ void cp16(void* s, const void* g) {
    unsigned sa = (unsigned)__cvta_generic_to_shared(s);
    asm volatile("cp.async.cg.shared.global [%0], [%1], 16;\n" :: "r"(sa), "l"(g));
}
#define CP_COMMIT() asm volatile("cp.async.commit_group;\n")
#define CP_WAIT(n)  asm volatile("cp.async.wait_group %0;\n" :: "n"(n) : "memory")

__device__ __forceinline__ void mma16816(float* c, const unsigned* a, const unsigned* b) {
    asm volatile(
        "mma.sync.aligned.m16n8k16.row.col.f32.f16.f16.f32 "
        "{%0,%1,%2,%3}, {%4,%5,%6,%7}, {%8,%9}, {%0,%1,%2,%3};\n"
        : "+f"(c[0]), "+f"(c[1]), "+f"(c[2]), "+f"(c[3])
        : "r"(a[0]), "r"(a[1]), "r"(a[2]), "r"(a[3]), "r"(b[0]), "r"(b[1]));
}
__device__ __forceinline__ void ldsm_x4(unsigned* r, const void* p) {
    unsigned a = (unsigned)__cvta_generic_to_shared(p);
    asm volatile("ldmatrix.sync.aligned.m8n8.x4.shared.b16 {%0,%1,%2,%3}, [%4];\n"
                 : "=r"(r[0]), "=r"(r[1]), "=r"(r[2]), "=r"(r[3]) : "r"(a));
}
__device__ __forceinline__ unsigned pack2h(float v0, float v1) {
    __half2 h = __floats2half2_rn(v0, v1);
    return *(unsigned*)&h;
}
__device__ __forceinline__ float ex2f(float x) {
    float y;
    asm("ex2.approx.ftz.f32 %0, %1;" : "=f"(y) : "f"(x));
    return y;
}

// ---------------------------------------------------------------------------
// fused prep (one launch)
// ---------------------------------------------------------------------------
#define PREP_BLOCKS 18444

__global__ void prep_all(const float* __restrict__ x,
                         const float* __restrict__ Wq, const float* __restrict__ Wk,
                         const float* __restrict__ Wv, const float* __restrict__ Wo,
                         const float* __restrict__ bq, const float* __restrict__ bk,
                         const float* __restrict__ bv,
                         __half* __restrict__ xh, __half* __restrict__ Wcat,
                         __half* __restrict__ Woh, float* __restrict__ bcat)
{
    int bid = blockIdx.x;
    int tx = threadIdx.x, ty = threadIdx.y;
    int tid = ty * 32 + tx;

    if (bid < 8192) {                                    // conv x
        size_t i = ((size_t)bid * 256 + tid) * 4;
        float4 v = *(const float4*)(x + i);
        *(__half2*)(xh + i)     = __floats2half2_rn(v.x, v.y);
        *(__half2*)(xh + i + 2) = __floats2half2_rn(v.z, v.w);
        return;
    }
    bid -= 8192;
    if (bid >= 10240) {                                  // bias concat
        int i = (bid - 10240) * 256 + tid;
        float v = (i < 2048) ? bq[i] : (i < 2560 ? bk[i - 2048] : bv[i - 2560]);
        bcat[i] = v;
        return;
    }
    const float* W; __half* T; int N, tilesX;
    if (bid < 4096)      { W = Wq; T = Wcat;             N = DM;  tilesX = 64; }
    else if (bid < 5120) { bid -= 4096; W = Wk; T = Wcat + 2048 * DM; N = KVW; tilesX = 16; }
    else if (bid < 6144) { bid -= 5120; W = Wv; T = Wcat + 2560 * DM; N = KVW; tilesX = 16; }
    else                 { bid -= 6144; W = Wo; T = Woh;              N = DM;  tilesX = 64; }

    __shared__ float t[32][33];
    int bx = (bid % tilesX) * 32;
    int by = (bid / tilesX) * 32;
#pragma unroll
    for (int i = 0; i < 32; i += 8)
        t[ty + i][tx] = W[(size_t)(by + ty + i) * N + bx + tx];
    __syncthreads();
#pragma unroll
    for (int i = 0; i < 32; i += 8)
        T[(size_t)(bx + ty + i) * DM + by + tx] = __float2half_rn(t[tx][ty + i]);
}

// ---------------------------------------------------------------------------
// fp16 GEMM: 128x128 tiles, warp tile 32x64, 4-stage ring, K-chunk 32,
// ONE sync per chunk, persistent perfectly-balanced grid of 256.
// stage = A 128x40 + B 128x40 halves = 20480B; 4 stages = 81920B
// ---------------------------------------------------------------------------
#define STG_H   10240
#define GEMM_SMEM (4 * STG_H * 2)  // 81920 bytes
#define GEMM_GRID 256

__global__ __launch_bounds__(256, 2) void gemm_fp16(
    const __half* __restrict__ Ah, const __half* __restrict__ Bh,
    const float* __restrict__ bias, float* __restrict__ Cf,
    __half* __restrict__ Qh, __half* __restrict__ Kh, __half* __restrict__ Vth,
    int mode, int N, int K, int mTiles, int totTiles)
{
    extern __shared__ __half sm[];
    const int tid = threadIdx.x;
    const int T = K >> 5;                 // 32-K chunks
    const int w = tid >> 5, l = tid & 31;
    const int wm = (w & 3) * 32;          // 4 M-slices of 32
    const int wn = (w >> 2) * 64;         // 2 N-slices of 64
    const int qr = l >> 2, qc = (l & 3) * 2;
    const int arow = (l & 7) + ((l >> 3) & 1) * 8;
    const int acol = (l >> 4) * 8;
    const int brow = (l & 7) + ((l >> 4) & 1) * 8;
    const int bcol = ((l >> 3) & 1) * 8;

    for (int tIdx = blockIdx.x; tIdx < totTiles; tIdx += gridDim.x) {
        const int bm = (tIdx % mTiles) * 128;
        const int bn = (tIdx / mTiles) * 128;

        auto load_stage = [&](int s, int k0) {
            __half* base = sm + s * STG_H;
#pragma unroll
            for (int t = 0; t < 4; t++) {
                int c = tid + t * 256;                  // 0..1023
                if (c < 512) {                          // A: 128 rows x 32 halves
                    int row = c >> 2, seg = (c & 3) * 8;
                    cp16(base + row * 40 + seg,
                         Ah + (size_t)(bm + row) * K + k0 + seg);
                } else {                                // B: 128 rows x 32 halves
                    int j = c - 512;
                    int row = j >> 2, seg = (j & 3) * 8;
                    cp16(base + 5120 + row * 40 + seg,
                         Bh + (size_t)(bn + row) * K + k0 + seg);
                }
            }
        };

        float acc[2][8][4];
#pragma unroll
        for (int mi = 0; mi < 2; mi++)
#pragma unroll
            for (int ni = 0; ni < 8; ni++)
#pragma unroll
                for (int r = 0; r < 4; r++) acc[mi][ni][r] = 0.f;

        load_stage(0, 0);  CP_COMMIT();
        load_stage(1, 32); CP_COMMIT();
        load_stage(2, 64); CP_COMMIT();

        int sIdx = 0;
        for (int i = 0; i < T; i++) {
            if (i <= T - 3)      CP_WAIT(2);
            else if (i == T - 2) CP_WAIT(1);
            else                 CP_WAIT(0);
            __syncthreads();
            if (i + 3 < T) {   // refill stage (i+3)%4 == (i-1)%4 (readers done at sync)
                int ls = sIdx + 3; if (ls >= 4) ls -= 4;
                load_stage(ls, (i + 3) * 32);
                CP_COMMIT();
            }

            const __half* Ahs = sm + sIdx * STG_H;
            const __half* Bhs = Ahs + 5120;

#pragma unroll
            for (int ks = 0; ks < 32; ks += 16) {
                unsigned ah[2][4];
#pragma unroll
                for (int mi = 0; mi < 2; mi++)
                    ldsm_x4(ah[mi], Ahs + (wm + mi * 16 + arow) * 40 + ks + acol);
#pragma unroll
                for (int p = 0; p < 4; p++) {
                    unsigned bh[4];
                    ldsm_x4(bh, Bhs + (wn + p * 16 + brow) * 40 + ks + bcol);
#pragma unroll
                    for (int mi = 0; mi < 2; mi++) {
                        mma16816(acc[mi][2 * p],     ah[mi], bh);
                        mma16816(acc[mi][2 * p + 1], ah[mi], bh + 2);
                    }
                }
            }
            if (++sIdx == 4) sIdx = 0;
        }

#pragma unroll
        for (int mi = 0; mi < 2; mi++) {
#pragma unroll
            for (int ni = 0; ni < 8; ni++) {
                int r  = bm + wm + mi * 16 + qr;
                int cc = bn + wn + ni * 8 + qc;
                float b0 = bias[cc], b1 = bias[cc + 1];
                float v0 = acc[mi][ni][0] + b0, v1 = acc[mi][ni][1] + b1;
                float v2 = acc[mi][ni][2] + b0, v3 = acc[mi][ni][3] + b1;
                if (mode == 0) {
                    *(float2*)(Cf + (size_t)r * N + cc)       = make_float2(v0, v1);
                    *(float2*)(Cf + (size_t)(r + 8) * N + cc) = make_float2(v2, v3);
                } else if (cc < 2048) {             // Q
                    *(unsigned*)(Qh + (size_t)r * DM + cc)       = pack2h(v0, v1);
                    *(unsigned*)(Qh + (size_t)(r + 8) * DM + cc) = pack2h(v2, v3);
                } else if (cc < 2560) {             // K
                    int col = cc - 2048;
                    *(unsigned*)(Kh + (size_t)r * KVW + col)       = pack2h(v0, v1);
                    *(unsigned*)(Kh + (size_t)(r + 8) * KVW + col) = pack2h(v2, v3);
                } else {                            // V transposed [b][dk][s]
                    int col = cc - 2560;
                    int bb = r >> 11, sl = r & (S_LEN - 1);
                    size_t base = ((size_t)bb * KVW + col) * S_LEN;
                    Vth[base + sl]             = __float2half_rn(v0);
                    Vth[base + S_LEN + sl]     = __float2half_rn(v1);
                    Vth[base + sl + 8]         = __float2half_rn(v2);
                    Vth[base + S_LEN + sl + 8] = __float2half_rn(v3);
                }
            }
        }
        __syncthreads();
    }
}

// ---------------------------------------------------------------------------
// fp16 flash attention (causal, GQA) — unchanged from R16
// ---------------------------------------------------------------------------
#define FL_SMEM ((9216 + 3 * 9216) * 2)   // 73728 bytes

__global__ __launch_bounds__(256, 2) void gqa_flash_fp16(
    const __half* __restrict__ Qh_g, const __half* __restrict__ Kh_g,
    const __half* __restrict__ Vth_g, __half* __restrict__ Ch_g)
{
    extern __shared__ __half sb[];
    const int tid = threadIdx.x;
    const int w = tid >> 5, l = tid & 31;
    const int qr = l >> 2, qc = (l & 3) * 2;
    const int arow = (l & 7) + ((l >> 3) & 1) * 8;
    const int acol = (l >> 4) * 8;
    const int brow = (l & 7) + ((l >> 4) & 1) * 8;
    const int bcol = ((l >> 3) & 1) * 8;
    const int mtile = (gridDim.x - 1) - blockIdx.x;
    const int h = blockIdx.y, b = blockIdx.z;
    const int kvh = h >> 2;
    const int m0 = mtile * 128;
    const int kvTiles = 2 * mtile + 2;
    const int lastTile = 2 * mtile + (w >> 2);

    const __half* Qph = Qh_g + ((size_t)(b * S_LEN + m0)) * DM + h * 64;
#pragma unroll
    for (int t = 0; t < 4; t++) {
        int idx = tid + t * 256;
        int row = idx >> 3, seg = (idx & 7) * 8;
        cp16(sb + row * 72 + seg, Qph + (size_t)row * DM + seg);
    }

    auto load_kv = [&](int sidx, int jt) {
        __half* st = sb + 9216 + sidx * 9216;
        const int k0 = jt * 64;
        const __half* Kg = Kh_g + ((size_t)(b * S_LEN + k0)) * KVW + kvh * 64;
        const __half* Vg = Vth_g + ((size_t)b * KVW + kvh * 64) * S_LEN + k0;
#pragma unroll
        for (int t = 0; t < 2; t++) {
            int idx = tid + t * 256;
            int row = idx >> 3, seg = (idx & 7) * 8;
            cp16(st + row * 72 + seg,        Kg + (size_t)row * KVW + seg);
            cp16(st + 4608 + row * 72 + seg, Vg + (size_t)row * S_LEN + seg);
        }
    };

    load_kv(0, 0); CP_COMMIT();
    load_kv(1, 1); CP_COMMIT();

    unsigned aqh[4][4];
    float o[8][4];
#pragma unroll
    for (int n = 0; n < 8; n++)
#pragma unroll
        for (int r = 0; r < 4; r++) o[n][r] = 0.f;
    float mrow0 = -INFINITY, mrow1 = -INFINITY, lrow0 = 0.f, lrow1 = 0.f;

    const int r0 = m0 + w * 16 + qr;
    const int r1 = r0 + 8;

    int sIdx = 0;
    for (int jt = 0; jt < kvTiles; jt++) {
        if (jt < kvTiles - 1) CP_WAIT(1);
        else                  CP_WAIT(0);
        __syncthreads();
        if (jt + 2 < kvTiles) {
            int ls = sIdx + 2; if (ls >= 3) ls -= 3;
            load_kv(ls, jt + 2);
            CP_COMMIT();
        }
        if (jt == 0) {
#pragma unroll
            for (int j = 0; j < 4; j++)
                ldsm_x4(aqh[j], sb + (w * 16 + arow) * 72 + j * 16 + acol);
        }
        const __half* st = sb + 9216 + sIdx * 9216;

        if (jt <= lastTile) {
            const int k0 = jt * 64;
            float s[8][4];
#pragma unroll
            for (int n = 0; n < 8; n++)
#pragma unroll
                for (int r = 0; r < 4; r++) s[n][r] = 0.f;

#pragma unroll
            for (int j = 0; j < 4; j++) {
#pragma unroll
                for (int p = 0; p < 4; p++) {
                    unsigned bh[4];
                    ldsm_x4(bh, st + (p * 16 + brow) * 72 + j * 16 + bcol);
                    mma16816(s[2 * p],     aqh[j], bh);
                    mma16816(s[2 * p + 1], aqh[j], bh + 2);
                }
            }

            const float rs = 0.18033688f;   // log2(e)/8
            if (k0 + 63 > m0 + w * 16) {
#pragma unroll
                for (int n = 0; n < 8; n++) {
                    int c0 = k0 + n * 8 + qc;
                    s[n][0] = (c0     > r0) ? -1e30f : s[n][0] * rs;
                    s[n][1] = (c0 + 1 > r0) ? -1e30f : s[n][1] * rs;
                    s[n][2] = (c0     > r1) ? -1e30f : s[n][2] * rs;
                    s[n][3] = (c0 + 1 > r1) ? -1e30f : s[n][3] * rs;
                }
            } else {
#pragma unroll
                for (int n = 0; n < 8; n++)
#pragma unroll
                    for (int r = 0; r < 4; r++) s[n][r] *= rs;
            }

            float mx0 = -1e30f, mx1 = -1e30f;
#pragma unroll
            for (int n = 0; n < 8; n++) {
                mx0 = fmaxf(mx0, fmaxf(s[n][0], s[n][1]));
                mx1 = fmaxf(mx1, fmaxf(s[n][2], s[n][3]));
            }
            mx0 = fmaxf(mx0, __shfl_xor_sync(0xffffffffu, mx0, 1));
            mx0 = fmaxf(mx0, __shfl_xor_sync(0xffffffffu, mx0, 2));
            mx1 = fmaxf(mx1, __shfl_xor_sync(0xffffffffu, mx1, 1));
            mx1 = fmaxf(mx1, __shfl_xor_sync(0xffffffffu, mx1, 2));
            float mn0 = fmaxf(mrow0, mx0), mn1 = fmaxf(mrow1, mx1);
            float cr0 = ex2f(mrow0 - mn0), cr1 = ex2f(mrow1 - mn1);
            float sum0 = 0.f, sum1 = 0.f;
#pragma unroll
            for (int n = 0; n < 8; n++) {
                s[n][0] = ex2f(s[n][0] - mn0);
                s[n][1] = ex2f(s[n][1] - mn0);
                s[n][2] = ex2f(s[n][2] - mn1);
                s[n][3] = ex2f(s[n][3] - mn1);
                sum0 += s[n][0] + s[n][1];
                sum1 += s[n][2] + s[n][3];
            }
            sum0 += __shfl_xor_sync(0xffffffffu, sum0, 1);
            sum0 += __shfl_xor_sync(0xffffffffu, sum0, 2);
            sum1 += __shfl_xor_sync(0xffffffffu, sum1, 1);
            sum1 += __shfl_xor_sync(0xffffffffu, sum1, 2);
            lrow0 = lrow0 * cr0 + sum0;
            lrow1 = lrow1 * cr1 + sum1;
            mrow0 = mn0; mrow1 = mn1;
#pragma unroll
            for (int n = 0; n < 8; n++) {
                o[n][0] *= cr0; o[n][1] *= cr0;
                o[n][2] *= cr1; o[n][3] *= cr1;
            }

            unsigned pah[4][4];
#pragma unroll
            for (int j = 0; j < 4; j++) {
                pah[j][0] = pack2h(s[2 * j][0],     s[2 * j][1]);
                pah[j][1] = pack2h(s[2 * j][2],     s[2 * j][3]);
                pah[j][2] = pack2h(s[2 * j + 1][0], s[2 * j + 1][1]);
                pah[j][3] = pack2h(s[2 * j + 1][2], s[2 * j + 1][3]);
            }

#pragma unroll
            for (int j = 0; j < 4; j++) {
#pragma unroll
                for (int p = 0; p < 4; p++) {
                    unsigned bh[4];
                    ldsm_x4(bh, st + 4608 + (p * 16 + brow) * 72 + j * 16 + bcol);
                    mma16816(o[2 * p],     pah[j], bh);
                    mma16816(o[2 * p + 1], pah[j], bh + 2);
                }
            }
        }
        if (++sIdx == 3) sIdx = 0;
    }

    float inv0 = 1.f / lrow0, inv1 = 1.f / lrow1;
    size_t base0 = ((size_t)(b * S_LEN) + r0) * DM + h * 64;
    size_t base1 = ((size_t)(b * S_LEN) + r1) * DM + h * 64;
#pragma unroll
    for (int n = 0; n < 8; n++) {
        *(__half2*)(Ch_g + base0 + n * 8 + qc) = __floats2half2_rn(o[n][0] * inv0, o[n][1] * inv0);
        *(__half2*)(Ch_g + base1 + n * 8 + qc) = __floats2half2_rn(o[n][2] * inv1, o[n][3] * inv1);
    }
}

// ---------------------------------------------------------------------------
extern "C" void kernel_launch(void* const* d_in, const int* in_sizes, int n_in,
                              void* d_out, int out_size)
{
    (void)in_sizes; (void)n_in; (void)out_size;
    const float* x  = (const float*)d_in[0];
    const float* Wq = (const float*)d_in[2];
    const float* bq = (const float*)d_in[3];
    const float* Wk = (const float*)d_in[4];
    const float* bk = (const float*)d_in[5];
    const float* Wv = (const float*)d_in[6];
    const float* bv = (const float*)d_in[7];
    const float* Wo = (const float*)d_in[8];
    const float* bo = (const float*)d_in[9];
    float* out = (float*)d_out;

    __half *xh, *Qh, *Kh, *Vth, *Ch, *Wcat, *Woh;
    float* bcat;
    cudaGetSymbolAddress((void**)&xh, g_xh);
    cudaGetSymbolAddress((void**)&Qh, g_Qh);
    cudaGetSymbolAddress((void**)&Kh, g_Kh);
    cudaGetSymbolAddress((void**)&Vth, g_Vth);
    cudaGetSymbolAddress((void**)&Ch, g_Ch);
    cudaGetSymbolAddress((void**)&Wcat, g_Wcat);
    cudaGetSymbolAddress((void**)&Woh, g_Woh);
    cudaGetSymbolAddress((void**)&bcat, g_bcat);

    cudaFuncSetAttribute(gemm_fp16,
                         cudaFuncAttributeMaxDynamicSharedMemorySize, GEMM_SMEM);
    cudaFuncSetAttribute(gqa_flash_fp16,
                         cudaFuncAttributeMaxDynamicSharedMemorySize, FL_SMEM);

    // fused prep
    prep_all<<<PREP_BLOCKS, dim3(32, 8)>>>(x, Wq, Wk, Wv, Wo, bq, bk, bv,
                                           xh, Wcat, Woh, bcat);

    // fused QKV projection: tiles 128x128 -> 32 x 24 = 768 (exactly 3/block)
    gemm_fp16<<<GEMM_GRID, 256, GEMM_SMEM>>>(
        xh, Wcat, bcat, nullptr, Qh, Kh, Vth, 1, NCAT, DM, 32, 768);

    // attention
    gqa_flash_fp16<<<dim3(S_LEN / 128, NH, B_SZ), 256, FL_SMEM>>>(
        Qh, Kh, Vth, Ch);

    // output projection: tiles 128x128 -> 32 x 16 = 512 (exactly 2/block)
    gemm_fp16<<<GEMM_GRID, 256, GEMM_SMEM>>>(
        Ch, Woh, bo, out, nullptr, nullptr, nullptr, 0, DM, DM, 32, 512);
}